// round 13
// baseline (speedup 1.0000x reference)
#include <cuda_runtime.h>
#include <math.h>
#include <stdint.h>

// ---------------- problem constants ----------------
#define BQ   4
#define LQn  1024
#define CC   256
#define HH   8
#define DFFn 1024
#define LSRC 21760
#define M1   (BQ * LQn)     // 4096 query rows
#define MS   (BQ * LSRC)    // 87040 source rows

typedef unsigned long long u64;

// ---------------- scratch (static device global, no allocs) ----------------
static constexpr size_t OF_QK  = 0;
static constexpr size_t OF_QKP = OF_QK  + (size_t)M1 * CC;      // Q|K packed, 512 cols
static constexpr size_t OF_V   = OF_QKP + (size_t)M1 * 512;
static constexpr size_t OF_ATT = OF_V   + (size_t)M1 * CC;
static constexpr size_t OF_TGA = OF_ATT + (size_t)M1 * CC;
static constexpr size_t OF_Q2  = OF_TGA + (size_t)M1 * CC;
static constexpr size_t OF_VAL = OF_Q2  + (size_t)M1 * CC;
static constexpr size_t OF_DFO = OF_VAL + (size_t)MS * CC;
static constexpr size_t OF_OFW = OF_DFO + (size_t)M1 * CC;      // off|aw out, stride 384
static constexpr size_t OF_TMP = OF_OFW + (size_t)M1 * 384;
static constexpr size_t OF_TGB = OF_TMP + (size_t)M1 * CC;
static constexpr size_t OF_FFH = OF_TGB + (size_t)M1 * CC;
// ---- contiguous pre-rounded block (filled by prep_kernel, in this order) ----
static constexpr size_t OF_TGR = OF_FFH + (size_t)M1 * DFFn;    // rounded tgt [M1*CC]
static constexpr size_t OF_WIN = OF_TGR + (size_t)M1 * CC;      // rounded in_w [768*CC]
static constexpr size_t OF_SAW = OF_WIN + (size_t)768 * CC;     // rounded sa_w
static constexpr size_t OF_COW = OF_SAW + (size_t)256 * CC;     // rounded co_w
static constexpr size_t OF_F2W = OF_COW + (size_t)256 * CC;     // rounded f2_w [256*1024]
static constexpr size_t OF_WCT = OF_F2W + (size_t)256 * DFFn;   // rounded off_w|aw_w [384*CC]
static constexpr size_t OF_BCT = OF_WCT + (size_t)384 * CC;     // rounded off_b|aw_b [384]
static constexpr size_t SCRATCH_TOTAL = OF_BCT + 384;

__device__ __align__(16) float g_scratch[SCRATCH_TOTAL];

// ---------------- small helpers ----------------
__device__ __forceinline__ unsigned cvt_tf32(float x) {
    unsigned r;
    asm("cvt.rna.tf32.f32 %0, %1;" : "=r"(r) : "f"(x));
    return r;
}
__device__ __forceinline__ float rnd_tf32(float x) {
    return __uint_as_float(cvt_tf32(x));
}
__device__ __forceinline__ u64 f2fma(u64 a, u64 b, u64 c) {
    u64 d;
    asm("fma.rn.f32x2 %0, %1, %2, %3;" : "=l"(d) : "l"(a), "l"(b), "l"(c));
    return d;
}
__device__ __forceinline__ u64 f2mul(u64 a, u64 b) {
    u64 d;
    asm("mul.rn.f32x2 %0, %1, %2;" : "=l"(d) : "l"(a), "l"(b));
    return d;
}
__device__ __forceinline__ u64 f2pack(float lo, float hi) {
    u64 d;
    asm("mov.b64 %0, {%1, %2};" : "=l"(d) : "f"(lo), "f"(hi));
    return d;
}
__device__ __forceinline__ float2 f2unpack(u64 v) {
    float2 r;
    asm("mov.b64 {%0, %1}, %2;" : "=f"(r.x), "=f"(r.y) : "l"(v));
    return r;
}
__device__ __forceinline__ void cp_async16(void* s, const void* g) {
    unsigned sa = (unsigned)__cvta_generic_to_shared(s);
    asm volatile("cp.async.ca.shared.global [%0], [%1], 16;" :: "r"(sa), "l"(g));
}

// ---------------- prep: round tgt + gemm64 weights into scratch --------------
// dest is the contiguous block starting at OF_TGR; source picked by range.
// float4-unit boundaries:
//   tgt 262144 | in_w 311296 | sa_w 327680 | co_w 344064 | f2_w 409600
//   off_w 425984 | aw_w 434176 | off_b 434240 | aw_b 434272
__global__ void prep_kernel(const float4* __restrict__ tgt,
                            const float4* __restrict__ in_w,
                            const float4* __restrict__ sa_w,
                            const float4* __restrict__ co_w,
                            const float4* __restrict__ f2_w,
                            const float4* __restrict__ off_w,
                            const float4* __restrict__ aw_w,
                            const float4* __restrict__ off_b,
                            const float4* __restrict__ aw_b,
                            float4* __restrict__ dst) {
    const int i = blockIdx.x * blockDim.x + threadIdx.x;
    if (i >= 434272) return;
    const float4* src;
    int off;
    if (i < 262144)      { src = tgt;   off = i; }
    else if (i < 311296) { src = in_w;  off = i - 262144; }
    else if (i < 327680) { src = sa_w;  off = i - 311296; }
    else if (i < 344064) { src = co_w;  off = i - 327680; }
    else if (i < 409600) { src = f2_w;  off = i - 344064; }
    else if (i < 425984) { src = off_w; off = i - 409600; }
    else if (i < 434176) { src = aw_w;  off = i - 425984; }
    else if (i < 434240) { src = off_b; off = i - 434176; }
    else                 { src = aw_b;  off = i - 434240; }
    float4 v = src[off];
    v.x = rnd_tf32(v.x); v.y = rnd_tf32(v.y);
    v.z = rnd_tf32(v.z); v.w = rnd_tf32(v.w);
    dst[i] = v;
}

// ---------------- elementwise add (float4), output tf32-rounded -------------
__global__ void add_vec_kernel(const float4* __restrict__ a,
                               const float4* __restrict__ b,
                               float4* __restrict__ o, int n4) {
    int i = blockIdx.x * blockDim.x + threadIdx.x;
    if (i < n4) {
        float4 x = a[i], y = b[i];
        float4 r;
        r.x = rnd_tf32(x.x + y.x); r.y = rnd_tf32(x.y + y.y);
        r.z = rnd_tf32(x.z + y.z); r.w = rnd_tf32(x.w + y.w);
        o[i] = r;
    }
}

// ---------------- tf32 tensor-core GEMM, 128x128 tiles, 3-stage --------------
// ACT: relu + tf32-round the output (f1 path; its consumer is a no-cvt gemm64)
template <int ACT>
__global__ void __launch_bounds__(256, 2) tf32_gemm_kernel(
    const float* __restrict__ A, const float* __restrict__ W,
    const float* __restrict__ bias, float* __restrict__ C,
    int K, int N) {
    __shared__ __align__(16) float sA[3][128 * 20];
    __shared__ __align__(16) float sB[3][128 * 20];

    const int tid = threadIdx.x;
    const int m0 = blockIdx.y << 7;
    const int n0 = blockIdx.x << 7;
    const int warp = tid >> 5, lane = tid & 31;
    const int wm = warp >> 2, wn = warp & 3;      // 2 x 4 warp grid
    const int grp = lane >> 2, qid = lane & 3;

    float acc[4][4][4];
#pragma unroll
    for (int mi = 0; mi < 4; ++mi)
#pragma unroll
        for (int ni = 0; ni < 4; ++ni)
#pragma unroll
            for (int r = 0; r < 4; ++r) acc[mi][ni][r] = 0.f;

    const int srow = tid >> 2;            // 0..63
    const int scol = (tid & 3) << 2;      // 0,4,8,12

    const float* Abase = A + (size_t)m0 * K;
    const float* Bbase = W + (size_t)n0 * K;

#define LOAD128(t, buf)                                                     \
    do {                                                                    \
        const float* Ab = Abase + (size_t)(t) * 16;                         \
        const float* Bb = Bbase + (size_t)(t) * 16;                         \
        _Pragma("unroll")                                                   \
        for (int i = 0; i < 2; ++i) {                                       \
            int row = i * 64 + srow;                                        \
            cp_async16(&sA[buf][row * 20 + scol], Ab + (size_t)row * K + scol); \
            cp_async16(&sB[buf][row * 20 + scol], Bb + (size_t)row * K + scol); \
        }                                                                   \
    } while (0)

    const int T = K >> 4;
    LOAD128(0, 0);
    asm volatile("cp.async.commit_group;" ::: "memory");
    LOAD128(1, 1);
    asm volatile("cp.async.commit_group;" ::: "memory");

    for (int t = 0; t < T; ++t) {
        asm volatile("cp.async.wait_group 1;" ::: "memory");
        __syncthreads();

        const float* As = sA[t % 3];
        const float* Bs = sB[t % 3];
#pragma unroll
        for (int s = 0; s < 2; ++s) {
            const int k0 = s << 3;
            unsigned a[4][4], b[4][2];
#pragma unroll
            for (int mi = 0; mi < 4; ++mi) {
                const int r = wm * 64 + mi * 16 + grp;
                a[mi][0] = cvt_tf32(As[r * 20 + k0 + qid]);
                a[mi][1] = cvt_tf32(As[(r + 8) * 20 + k0 + qid]);
                a[mi][2] = cvt_tf32(As[r * 20 + k0 + qid + 4]);
                a[mi][3] = cvt_tf32(As[(r + 8) * 20 + k0 + qid + 4]);
            }
#pragma unroll
            for (int ni = 0; ni < 4; ++ni) {
                const int rB = wn * 32 + ni * 8 + grp;
                b[ni][0] = cvt_tf32(Bs[rB * 20 + k0 + qid]);
                b[ni][1] = cvt_tf32(Bs[rB * 20 + k0 + qid + 4]);
            }
#pragma unroll
            for (int mi = 0; mi < 4; ++mi)
#pragma unroll
                for (int ni = 0; ni < 4; ++ni) {
                    asm volatile(
                        "mma.sync.aligned.m16n8k8.row.col.f32.tf32.tf32.f32 "
                        "{%0,%1,%2,%3}, {%4,%5,%6,%7}, {%8,%9}, {%0,%1,%2,%3};"
                        : "+f"(acc[mi][ni][0]), "+f"(acc[mi][ni][1]),
                          "+f"(acc[mi][ni][2]), "+f"(acc[mi][ni][3])
                        : "r"(a[mi][0]), "r"(a[mi][1]), "r"(a[mi][2]),
                          "r"(a[mi][3]), "r"(b[ni][0]), "r"(b[ni][1]));
                }
        }
        const int tn = t + 2;
        if (tn < T) LOAD128(tn, tn % 3);
        asm volatile("cp.async.commit_group;" ::: "memory");
    }
#undef LOAD128

#pragma unroll
    for (int mi = 0; mi < 4; ++mi) {
        const int row = m0 + wm * 64 + mi * 16 + grp;
#pragma unroll
        for (int ni = 0; ni < 4; ++ni) {
            const int col = n0 + wn * 32 + ni * 8 + (qid << 1);
            const float2 bb = *(const float2*)(bias + col);
            float2 v0, v1;
            v0.x = acc[mi][ni][0] + bb.x; v0.y = acc[mi][ni][1] + bb.y;
            v1.x = acc[mi][ni][2] + bb.x; v1.y = acc[mi][ni][3] + bb.y;
            if (ACT) {
                v0.x = rnd_tf32(fmaxf(v0.x, 0.f));
                v0.y = rnd_tf32(fmaxf(v0.y, 0.f));
                v1.x = rnd_tf32(fmaxf(v1.x, 0.f));
                v1.y = rnd_tf32(fmaxf(v1.y, 0.f));
            }
            *(float2*)(C + (size_t)row * N + col) = v0;
            *(float2*)(C + (size_t)(row + 8) * N + col) = v1;
        }
    }
}

// ---------------- tf32 GEMM, 64x64 tiles, 256 threads, 4-stage, NO cvt ------
// All inputs MUST be pre-rounded to tf32 (low mantissa bits zero) — fragments
// go straight from LDS to mma.sync.
template <int ACT>
__global__ void __launch_bounds__(256) tf32_gemm64_kernel(
    const float* __restrict__ A, const float* __restrict__ W,
    const float* __restrict__ bias, float* __restrict__ C,
    int K, int N) {
    __shared__ __align__(16) float sA[4][64 * 20];
    __shared__ __align__(16) float sB[4][64 * 20];

    const int tid = threadIdx.x;
    const int m0 = blockIdx.y << 6;
    const int n0 = blockIdx.x << 6;
    const int warp = tid >> 5, lane = tid & 31;
    const int wm = warp >> 2, wn = warp & 3;      // 2 x 4 warp grid
    const int grp = lane >> 2, qid = lane & 3;
    const int srow = tid >> 2;            // 0..63
    const int scol = (tid & 3) << 2;      // 0,4,8,12

    const float* Abase = A + (size_t)m0 * K;
    const float* Bbase = W + (size_t)n0 * K;

    float acc[2][2][4];
#pragma unroll
    for (int mi = 0; mi < 2; ++mi)
#pragma unroll
        for (int ni = 0; ni < 2; ++ni)
#pragma unroll
            for (int r = 0; r < 4; ++r) acc[mi][ni][r] = 0.f;

#define LOAD64(t, buf)                                                       \
    do {                                                                     \
        const float* Ab = Abase + (size_t)(t) * 16;                          \
        const float* Bb = Bbase + (size_t)(t) * 16;                          \
        cp_async16(&sA[buf][srow * 20 + scol], Ab + (size_t)srow * K + scol);\
        cp_async16(&sB[buf][srow * 20 + scol], Bb + (size_t)srow * K + scol);\
    } while (0)

    const int T = K >> 4;
    LOAD64(0, 0);
    asm volatile("cp.async.commit_group;" ::: "memory");
    LOAD64(1, 1);
    asm volatile("cp.async.commit_group;" ::: "memory");
    LOAD64(2, 2);
    asm volatile("cp.async.commit_group;" ::: "memory");

    for (int t = 0; t < T; ++t) {
        asm volatile("cp.async.wait_group 2;" ::: "memory");
        __syncthreads();

        const float* As = sA[t & 3];
        const float* Bs = sB[t & 3];
#pragma unroll
        for (int s = 0; s < 2; ++s) {
            const int k0 = s << 3;
            unsigned a[2][4], b[2][2];
#pragma unroll
            for (int mi = 0; mi < 2; ++mi) {
                const int r = wm * 32 + mi * 16 + grp;
                a[mi][0] = __float_as_uint(As[r * 20 + k0 + qid]);
                a[mi][1] = __float_as_uint(As[(r + 8) * 20 + k0 + qid]);
                a[mi][2] = __float_as_uint(As[r * 20 + k0 + qid + 4]);
                a[mi][3] = __float_as_uint(As[(r + 8) * 20 + k0 + qid + 4]);
            }
#pragma unroll
            for (int ni = 0; ni < 2; ++ni) {
                const int rB = wn * 16 + ni * 8 + grp;
                b[ni][0] = __float_as_uint(Bs[rB * 20 + k0 + qid]);
                b[ni][1] = __float_as_uint(Bs[rB * 20 + k0 + qid + 4]);
            }
#pragma unroll
            for (int mi = 0; mi < 2; ++mi)
#pragma unroll
                for (int ni = 0; ni < 2; ++ni) {
                    asm volatile(
                        "mma.sync.aligned.m16n8k8.row.col.f32.tf32.tf32.f32 "
                        "{%0,%1,%2,%3}, {%4,%5,%6,%7}, {%8,%9}, {%0,%1,%2,%3};"
                        : "+f"(acc[mi][ni][0]), "+f"(acc[mi][ni][1]),
                          "+f"(acc[mi][ni][2]), "+f"(acc[mi][ni][3])
                        : "r"(a[mi][0]), "r"(a[mi][1]), "r"(a[mi][2]),
                          "r"(a[mi][3]), "r"(b[ni][0]), "r"(b[ni][1]));
                }
        }
        const int tn = t + 3;
        if (tn < T) LOAD64(tn, tn & 3);
        asm volatile("cp.async.commit_group;" ::: "memory");
    }
#undef LOAD64

#pragma unroll
    for (int mi = 0; mi < 2; ++mi) {
        const int row = m0 + wm * 32 + mi * 16 + grp;
#pragma unroll
        for (int ni = 0; ni < 2; ++ni) {
            const int col = n0 + wn * 16 + ni * 8 + (qid << 1);
            const float2 bb = *(const float2*)(bias + col);
            float2 v0, v1;
            v0.x = acc[mi][ni][0] + bb.x; v0.y = acc[mi][ni][1] + bb.y;
            v1.x = acc[mi][ni][2] + bb.x; v1.y = acc[mi][ni][3] + bb.y;
            if (ACT) {
                v0.x = fmaxf(v0.x, 0.f); v0.y = fmaxf(v0.y, 0.f);
                v1.x = fmaxf(v1.x, 0.f); v1.y = fmaxf(v1.y, 0.f);
            }
            *(float2*)(C + (size_t)row * N + col) = v0;
            *(float2*)(C + (size_t)(row + 8) * N + col) = v1;
        }
    }
}

// ---------------- fused MHA attention, split-K (streaming softmax, f32x2) ---
// Output rounded to tf32 (feeds no-cvt gemm64).
__global__ void __launch_bounds__(128) mha_attn_kernel(
    const float* __restrict__ QK, const float* __restrict__ V,
    float* __restrict__ O) {
    const int b = blockIdx.z, h = blockIdx.y;
    const int q0 = blockIdx.x << 6;
    const int tq = threadIdx.x & 63;
    const int kh = threadIdx.x >> 6;   // 0 or 1

    __shared__ __align__(16) float sK[2][64][36];
    __shared__ __align__(16) float sV[2][64][36];

    const float scale = 0.17677669529663687f;  // 1/sqrt(32)
    u64 q2[16], o2[16];
    const float* qrow = QK + (size_t)(b * LQn + q0 + tq) * 512 + h * 32;
#pragma unroll
    for (int i = 0; i < 8; ++i) {
        float4 v4 = *(const float4*)(qrow + i * 4);
        q2[2 * i]     = f2pack(v4.x * scale, v4.y * scale);
        q2[2 * i + 1] = f2pack(v4.z * scale, v4.w * scale);
        o2[2 * i] = 0ull; o2[2 * i + 1] = 0ull;
    }
    float m = -1e30f, l = 0.f;

    const int ktEnd = (kh + 1) * (LQn / 128);
#pragma unroll 1
    for (int kt = kh * (LQn / 128); kt < ktEnd; ++kt) {
        const int krow = (kt << 6) + tq;
        const float* kr = QK + (size_t)(b * LQn + krow) * 512 + 256 + h * 32;
        const float* vr = V + (size_t)(b * LQn + krow) * 256 + h * 32;
#pragma unroll
        for (int d = 0; d < 32; d += 4) {
            *(float4*)&sK[kh][tq][d] = *(const float4*)(kr + d);
            *(float4*)&sV[kh][tq][d] = *(const float4*)(vr + d);
        }
        __syncthreads();

#pragma unroll 1
        for (int j0 = 0; j0 < 64; j0 += 8) {
            float s[8];
#pragma unroll
            for (int jj = 0; jj < 8; ++jj) {
                const ulonglong2* kp = (const ulonglong2*)&sK[kh][j0 + jj][0];
                u64 a0 = 0ull, a1 = 0ull;
#pragma unroll
                for (int i = 0; i < 8; ++i) {
                    ulonglong2 kk = kp[i];
                    a0 = f2fma(q2[2 * i], kk.x, a0);
                    a1 = f2fma(q2[2 * i + 1], kk.y, a1);
                }
                const float2 p0 = f2unpack(a0), p1 = f2unpack(a1);
                s[jj] = (p0.x + p0.y) + (p1.x + p1.y);
            }
            float mx = m;
#pragma unroll
            for (int jj = 0; jj < 8; ++jj) mx = fmaxf(mx, s[jj]);
            const float corr = __expf(m - mx);
            m = mx;
            l *= corr;
            const u64 c2 = f2pack(corr, corr);
#pragma unroll
            for (int i = 0; i < 16; ++i) o2[i] = f2mul(o2[i], c2);
#pragma unroll
            for (int jj = 0; jj < 8; ++jj) {
                const float e = __expf(s[jj] - m);
                l += e;
                const u64 e2 = f2pack(e, e);
                const ulonglong2* vp = (const ulonglong2*)&sV[kh][j0 + jj][0];
#pragma unroll
                for (int i = 0; i < 8; ++i) {
                    ulonglong2 vv = vp[i];
                    o2[2 * i]     = f2fma(e2, vv.x, o2[2 * i]);
                    o2[2 * i + 1] = f2fma(e2, vv.y, o2[2 * i + 1]);
                }
            }
        }
        __syncthreads();
    }

    // ---- merge the two key-half partials ----
    if (kh == 1) {
        sK[0][tq][0] = m;
        sK[0][tq][1] = l;
#pragma unroll
        for (int i = 0; i < 16; ++i)
            *(u64*)&sV[1][tq][2 * i] = o2[i];
    }
    __syncthreads();
    if (kh == 0) {
        const float m1 = sK[0][tq][0];
        const float l1 = sK[0][tq][1];
        const float M = fmaxf(m, m1);
        const float c0 = __expf(m - M);
        const float c1 = __expf(m1 - M);
        const float L = l * c0 + l1 * c1;
        const float inv = 1.f / L;
        const u64 c02 = f2pack(c0 * inv, c0 * inv);
        const u64 c12 = f2pack(c1 * inv, c1 * inv);
        float* orow = O + (size_t)(b * LQn + q0 + tq) * 256 + h * 32;
#pragma unroll
        for (int i = 0; i < 8; ++i) {
            u64 r0 = f2mul(o2[2 * i], c02);
            u64 r1 = f2mul(o2[2 * i + 1], c02);
            r0 = f2fma(*(const u64*)&sV[1][tq][4 * i], c12, r0);
            r1 = f2fma(*(const u64*)&sV[1][tq][4 * i + 2], c12, r1);
            const float2 a = f2unpack(r0);
            const float2 c = f2unpack(r1);
            float4 v4;
            v4.x = rnd_tf32(a.x); v4.y = rnd_tf32(a.y);
            v4.z = rnd_tf32(c.x); v4.w = rnd_tf32(c.y);
            *(float4*)(orow + i * 4) = v4;
        }
    }
}

// ---------------- residual add + LayerNorm (+ optional rounded pos copy) ----
template <int WPOS>
__global__ void __launch_bounds__(256) add_ln_kernel(
    const float* __restrict__ X, const float* __restrict__ R,
    const float* __restrict__ g, const float* __restrict__ bb,
    float* __restrict__ out,
    const float* __restrict__ pos, float* __restrict__ out2) {
    const int r = blockIdx.x, t = threadIdx.x;
    const float v = X[(size_t)r * CC + t] + R[(size_t)r * CC + t];
    float s = v, s2 = v * v;
#pragma unroll
    for (int off = 16; off; off >>= 1) {
        s  += __shfl_xor_sync(0xffffffffu, s,  off);
        s2 += __shfl_xor_sync(0xffffffffu, s2, off);
    }
    __shared__ float sh[8], sh2[8];
    const int w = t >> 5, ln = t & 31;
    if (ln == 0) { sh[w] = s; sh2[w] = s2; }
    __syncthreads();
    if (t == 0) {
        float a = 0.f, b2 = 0.f;
#pragma unroll
        for (int i = 0; i < 8; ++i) { a += sh[i]; b2 += sh2[i]; }
        const float mean = a * (1.f / 256.f);
        const float var = b2 * (1.f / 256.f) - mean * mean;
        sh[0] = mean;
        sh2[0] = rsqrtf(var + 1e-5f);
    }
    __syncthreads();
    const float mean = sh[0], inv = sh2[0];
    const float y = (v - mean) * inv * g[t] + bb[t];
    out[(size_t)r * CC + t] = y;
    if (WPOS)
        out2[(size_t)r * CC + t] = rnd_tf32(y + pos[(size_t)r * CC + t]);
}

// ---------------- MS deformable sampling (fused off|aw, rounded output) -----
__global__ void __launch_bounds__(256) deform_kernel(
    const float* __restrict__ value,   // [B*LSRC, 256]
    const float* __restrict__ offaw,   // [M1, 384]: cols 0..255 off, 256..383 aw
    const float* __restrict__ refp,    // [B, LQ, L, 2]
    float* __restrict__ out) {         // [M1, 256], tf32-rounded
    const int wid = blockIdx.x * 8 + (threadIdx.x >> 5);
    const int lane = threadIdx.x & 31;
    const int h = wid & 7;
    const int q = (wid >> 3) & 1023;
    const int b = wid >> 13;

    const float* rowp = offaw + (size_t)(b * LQn + q) * 384;
    const float* ar = rowp + 256 + h * 16;
    const float logit = (lane < 16) ? ar[lane] : -1e30f;
    float mx = logit;
#pragma unroll
    for (int o = 16; o; o >>= 1)
        mx = fmaxf(mx, __shfl_xor_sync(0xffffffffu, mx, o));
    float e = (lane < 16) ? __expf(logit - mx) : 0.f;
    float se = e;
#pragma unroll
    for (int o = 16; o; o >>= 1) se += __shfl_xor_sync(0xffffffffu, se, o);
    const float p = e / se;

    const int   SZ[4] = {128, 64, 32, 16};
    const int   ST[4] = {0, 16384, 20480, 21504};
    const float* offr = rowp + h * 32;
    const float* refr = refp + (size_t)(b * LQn + q) * 8;

    float acc = 0.f;
#pragma unroll
    for (int l = 0; l < 4; ++l) {
        const int Wl = SZ[l];
        const float Wf = (float)Wl;
        const float rx = refr[l * 2 + 0];
        const float ry = refr[l * 2 + 1];
        const float* vb =
            value + ((size_t)b * LSRC + ST[l]) * 256 + h * 32 + lane;
#pragma unroll
        for (int pt = 0; pt < 4; ++pt) {
            const float ox = offr[(l * 4 + pt) * 2 + 0];
            const float oy = offr[(l * 4 + pt) * 2 + 1];
            const float x = (rx + ox / Wf) * Wf - 0.5f;
            const float y = (ry + oy / Wf) * Wf - 0.5f;
            const float x0f = floorf(x), y0f = floorf(y);
            const int x0 = (int)x0f, y0 = (int)y0f;
            const float wx1 = x - x0f, wx0 = 1.f - wx1;
            const float wy1 = y - y0f, wy0 = 1.f - wy1;
            const float aw = __shfl_sync(0xffffffffu, p, l * 4 + pt);

            if ((unsigned)x0 < (unsigned)Wl && (unsigned)y0 < (unsigned)Wl)
                acc = fmaf(aw * (wx0 * wy0),
                           vb[((size_t)y0 * Wl + x0) * 256], acc);
            if ((unsigned)(x0 + 1) < (unsigned)Wl && (unsigned)y0 < (unsigned)Wl)
                acc = fmaf(aw * (wx1 * wy0),
                           vb[((size_t)y0 * Wl + x0 + 1) * 256], acc);
            if ((unsigned)x0 < (unsigned)Wl && (unsigned)(y0 + 1) < (unsigned)Wl)
                acc = fmaf(aw * (wx0 * wy1),
                           vb[((size_t)(y0 + 1) * Wl + x0) * 256], acc);
            if ((unsigned)(x0 + 1) < (unsigned)Wl &&
                (unsigned)(y0 + 1) < (unsigned)Wl)
                acc = fmaf(aw * (wx1 * wy1),
                           vb[((size_t)(y0 + 1) * Wl + x0 + 1) * 256], acc);
        }
    }
    out[(size_t)(b * LQn + q) * 256 + h * 32 + lane] = rnd_tf32(acc);
}

// ---------------- launch (serial, single stream) -----------------------------
extern "C" void kernel_launch(void* const* d_in, const int* in_sizes, int n_in,
                              void* d_out, int out_size) {
    const float* tgt   = (const float*)d_in[0];
    const float* qpos  = (const float*)d_in[1];
    const float* refp  = (const float*)d_in[2];
    const float* src   = (const float*)d_in[3];
    const float* in_w  = (const float*)d_in[4];
    const float* in_b  = (const float*)d_in[5];
    const float* sa_w  = (const float*)d_in[6];
    const float* sa_b  = (const float*)d_in[7];
    const float* off_w = (const float*)d_in[8];
    const float* off_b = (const float*)d_in[9];
    const float* aw_w  = (const float*)d_in[10];
    const float* aw_b  = (const float*)d_in[11];
    const float* val_w = (const float*)d_in[12];
    const float* val_b = (const float*)d_in[13];
    const float* co_w  = (const float*)d_in[14];
    const float* co_b  = (const float*)d_in[15];
    const float* ln1_g = (const float*)d_in[16];
    const float* ln1_b = (const float*)d_in[17];
    const float* ln2_g = (const float*)d_in[18];
    const float* ln2_b = (const float*)d_in[19];
    const float* ln3_g = (const float*)d_in[20];
    const float* ln3_b = (const float*)d_in[21];
    const float* f1_w  = (const float*)d_in[22];
    const float* f1_b  = (const float*)d_in[23];
    const float* f2_w  = (const float*)d_in[24];
    const float* f2_b  = (const float*)d_in[25];
    float* out = (float*)d_out;

    float* s = nullptr;
    cudaGetSymbolAddress((void**)&s, g_scratch);
    float* qk    = s + OF_QK;
    float* qkp   = s + OF_QKP;
    float* vbuf  = s + OF_V;
    float* attn  = s + OF_ATT;
    float* tgta  = s + OF_TGA;
    float* q2    = s + OF_Q2;
    float* value = s + OF_VAL;
    float* dfo   = s + OF_DFO;
    float* offaw = s + OF_OFW;
    float* tmp   = s + OF_TMP;
    float* tgtb  = s + OF_TGB;
    float* ffh   = s + OF_FFH;
    float* tgtr  = s + OF_TGR;
    float* win_r = s + OF_WIN;
    float* saw_r = s + OF_SAW;
    float* cow_r = s + OF_COW;
    float* f2w_r = s + OF_F2W;
    float* wcat  = s + OF_WCT;
    float* bcat  = s + OF_BCT;

    const int n4 = M1 * CC / 4;

    // (1) round tgt + all gemm64 weights into scratch
    prep_kernel<<<(434272 + 255) / 256, 256>>>(
        (const float4*)tgt, (const float4*)in_w, (const float4*)sa_w,
        (const float4*)co_w, (const float4*)f2_w, (const float4*)off_w,
        (const float4*)aw_w, (const float4*)off_b, (const float4*)aw_b,
        (float4*)tgtr);

    // --- self-attention block ---
    // (2) qk = round(tgt + qpos)
    add_vec_kernel<<<(n4 + 255) / 256, 256>>>(
        (const float4*)tgt, (const float4*)qpos, (float4*)qk, n4);
    // (3) qkp
    tf32_gemm64_kernel<0><<<dim3(512 / 64, M1 / 64), 256>>>(
        qk, win_r, in_b, qkp, CC, 512);
    // (4) vbuf
    tf32_gemm64_kernel<0><<<dim3(CC / 64, M1 / 64), 256>>>(
        tgtr, win_r + 512 * CC, in_b + 512, vbuf, CC, CC);
    // (5) mha
    mha_attn_kernel<<<dim3(LQn / 64, HH, BQ), 128>>>(qkp, vbuf, attn);
    // (6) value projection — placed here so ncu (-s 5) profiles it
    tf32_gemm_kernel<0><<<dim3(CC / 128, MS / 128), 256>>>(
        src, val_w, val_b, value, CC, CC);
    // (7) sa projection
    tf32_gemm64_kernel<0><<<dim3(CC / 64, M1 / 64), 256>>>(
        attn, saw_r, sa_b, tmp, CC, CC);
    // (8) fused: tgta = LN(tmp + tgt), q2 = round(tgta + qpos)
    add_ln_kernel<1><<<M1, 256>>>(tmp, tgt, ln2_g, ln2_b, tgta, qpos, q2);

    // --- deformable cross-attention block ---
    tf32_gemm64_kernel<0><<<dim3(384 / 64, M1 / 64), 256>>>(
        q2, wcat, bcat, offaw, CC, 384);
    deform_kernel<<<(BQ * LQn * HH) / 8, 256>>>(value, offaw, refp, dfo);
    tf32_gemm64_kernel<0><<<dim3(CC / 64, M1 / 64), 256>>>(
        dfo, cow_r, co_b, tmp, CC, CC);
    add_ln_kernel<0><<<M1, 256>>>(tmp, tgta, ln1_g, ln1_b, tgtb,
                                  nullptr, nullptr);

    // --- FFN block ---
    tf32_gemm_kernel<1><<<dim3(DFFn / 128, M1 / 128), 256>>>(
        tgtb, f1_w, f1_b, ffh, CC, DFFn);
    tf32_gemm64_kernel<0><<<dim3(CC / 64, M1 / 64), 256>>>(
        ffh, f2w_r, f2_b, tmp, DFFn, CC);
    add_ln_kernel<0><<<M1, 256>>>(tmp, tgtb, ln3_g, ln3_b, out,
                                  nullptr, nullptr);
}

// round 14
// speedup vs baseline: 1.0187x; 1.0187x over previous
#include <cuda_runtime.h>
#include <math.h>
#include <stdint.h>

// ---------------- problem constants ----------------
#define BQ   4
#define LQn  1024
#define CC   256
#define HH   8
#define DFFn 1024
#define LSRC 21760
#define M1   (BQ * LQn)     // 4096 query rows
#define MS   (BQ * LSRC)    // 87040 source rows

typedef unsigned long long u64;

// ---------------- scratch (static device global, no allocs) ----------------
static constexpr size_t OF_QK  = 0;
static constexpr size_t OF_QKP = OF_QK  + (size_t)M1 * CC;      // Q|K packed, 512 cols
static constexpr size_t OF_V   = OF_QKP + (size_t)M1 * 512;
static constexpr size_t OF_ATT = OF_V   + (size_t)M1 * CC;
static constexpr size_t OF_TGA = OF_ATT + (size_t)M1 * CC;
static constexpr size_t OF_Q2  = OF_TGA + (size_t)M1 * CC;
static constexpr size_t OF_VAL = OF_Q2  + (size_t)M1 * CC;
static constexpr size_t OF_DFO = OF_VAL + (size_t)MS * CC;
static constexpr size_t OF_OFW = OF_DFO + (size_t)M1 * CC;      // off|aw out, stride 384
static constexpr size_t OF_TMP = OF_OFW + (size_t)M1 * 384;
static constexpr size_t OF_TGB = OF_TMP + (size_t)M1 * CC;
static constexpr size_t OF_FFH = OF_TGB + (size_t)M1 * CC;
static constexpr size_t OF_WCT = OF_FFH + (size_t)M1 * DFFn;    // concat off_w|aw_w [384,256]
static constexpr size_t OF_BCT = OF_WCT + (size_t)384 * CC;     // concat bias [384]
static constexpr size_t SCRATCH_TOTAL = OF_BCT + 384;

__device__ __align__(16) float g_scratch[SCRATCH_TOTAL];

// ---------------- small helpers ----------------
__device__ __forceinline__ u64 f2fma(u64 a, u64 b, u64 c) {
    u64 d;
    asm("fma.rn.f32x2 %0, %1, %2, %3;" : "=l"(d) : "l"(a), "l"(b), "l"(c));
    return d;
}
__device__ __forceinline__ u64 f2mul(u64 a, u64 b) {
    u64 d;
    asm("mul.rn.f32x2 %0, %1, %2;" : "=l"(d) : "l"(a), "l"(b));
    return d;
}
__device__ __forceinline__ u64 f2pack(float lo, float hi) {
    u64 d;
    asm("mov.b64 %0, {%1, %2};" : "=l"(d) : "f"(lo), "f"(hi));
    return d;
}
__device__ __forceinline__ float2 f2unpack(u64 v) {
    float2 r;
    asm("mov.b64 {%0, %1}, %2;" : "=f"(r.x), "=f"(r.y) : "l"(v));
    return r;
}
__device__ __forceinline__ void cp_async16(void* s, const void* g) {
    unsigned sa = (unsigned)__cvta_generic_to_shared(s);
    asm volatile("cp.async.ca.shared.global [%0], [%1], 16;" :: "r"(sa), "l"(g));
}
// ldmatrix x4: four 8x8 b16 matrices; lane i supplies addr of row i%8 of matrix i/8.
__device__ __forceinline__ void ldsm_x4(unsigned* r, unsigned addr) {
    asm volatile(
        "ldmatrix.sync.aligned.m8n8.x4.shared.b16 {%0,%1,%2,%3}, [%4];"
        : "=r"(r[0]), "=r"(r[1]), "=r"(r[2]), "=r"(r[3]) : "r"(addr));
}
#define MMA_TF32(accp, a0, a1, a2, a3, b0, b1)                               \
    asm volatile(                                                            \
        "mma.sync.aligned.m16n8k8.row.col.f32.tf32.tf32.f32 "                \
        "{%0,%1,%2,%3}, {%4,%5,%6,%7}, {%8,%9}, {%0,%1,%2,%3};"              \
        : "+f"((accp)[0]), "+f"((accp)[1]), "+f"((accp)[2]), "+f"((accp)[3]) \
        : "r"(a0), "r"(a1), "r"(a2), "r"(a3), "r"(b0), "r"(b1))

// ---------------- elementwise add (float4) ----------------
__global__ void add_vec_kernel(const float4* __restrict__ a,
                               const float4* __restrict__ b,
                               float4* __restrict__ o, int n4) {
    int i = blockIdx.x * blockDim.x + threadIdx.x;
    if (i < n4) {
        float4 x = a[i], y = b[i];
        o[i] = make_float4(x.x + y.x, x.y + y.y, x.z + y.z, x.w + y.w);
    }
}

// ---------------- tf32 GEMM, 128x128 tiles, 3-stage, ldmatrix ---------------
// C[M,N] = A[M,K] @ W[N,K]^T + bias (optional ReLU). tf32 via HW truncation.
template <int ACT>
__global__ void __launch_bounds__(256, 2) tf32_gemm_kernel(
    const float* __restrict__ A, const float* __restrict__ W,
    const float* __restrict__ bias, float* __restrict__ C,
    int K, int N) {
    __shared__ __align__(16) float sA[3][128 * 20];
    __shared__ __align__(16) float sB[3][128 * 20];

    const int tid = threadIdx.x;
    const int m0 = blockIdx.y << 7;
    const int n0 = blockIdx.x << 7;
    const int warp = tid >> 5, lane = tid & 31;
    const int wm = warp >> 2, wn = warp & 3;      // 2 x 4 warp grid
    const int grp = lane >> 2, qid = lane & 3;

    const unsigned sA32 = (unsigned)__cvta_generic_to_shared(&sA[0][0]);
    const unsigned sB32 = (unsigned)__cvta_generic_to_shared(&sB[0][0]);
    const unsigned STG = 128 * 20 * 4;

    // ldmatrix per-lane offsets (bytes within a stage)
    // A(mi, s): row = wm*64+mi*16 + ((lane>>3)&1)*8 + (lane&7), colf = s*8 + (lane>>4)*4
    // B(ni):    row = wn*32+ni*8 + (lane&7),            colf = (lane>>3)*4  (covers k 0..15)
    unsigned aoff[4], boff[4];
#pragma unroll
    for (int mi = 0; mi < 4; ++mi)
        aoff[mi] = (unsigned)((wm * 64 + mi * 16 + ((lane >> 3) & 1) * 8 +
                               (lane & 7)) * 80 + ((lane >> 4) << 4));
#pragma unroll
    for (int ni = 0; ni < 4; ++ni)
        boff[ni] = (unsigned)((wn * 32 + ni * 8 + (lane & 7)) * 80 +
                              ((lane >> 3) << 4));

    float acc[4][4][4];
#pragma unroll
    for (int mi = 0; mi < 4; ++mi)
#pragma unroll
        for (int ni = 0; ni < 4; ++ni)
#pragma unroll
            for (int r = 0; r < 4; ++r) acc[mi][ni][r] = 0.f;

    const int srow = tid >> 2;            // 0..63
    const int scol = (tid & 3) << 2;      // 0,4,8,12
    const float* Abase = A + (size_t)m0 * K;
    const float* Bbase = W + (size_t)n0 * K;

#define LOAD128(t, buf)                                                     \
    do {                                                                    \
        const float* Ab = Abase + (size_t)(t) * 16;                         \
        const float* Bb = Bbase + (size_t)(t) * 16;                         \
        _Pragma("unroll")                                                   \
        for (int i = 0; i < 2; ++i) {                                       \
            int row = i * 64 + srow;                                        \
            cp_async16(&sA[buf][row * 20 + scol], Ab + (size_t)row * K + scol); \
            cp_async16(&sB[buf][row * 20 + scol], Bb + (size_t)row * K + scol); \
        }                                                                   \
    } while (0)

    const int T = K >> 4;
    LOAD128(0, 0);
    asm volatile("cp.async.commit_group;" ::: "memory");
    LOAD128(1, 1);
    asm volatile("cp.async.commit_group;" ::: "memory");

    for (int t = 0; t < T; ++t) {
        asm volatile("cp.async.wait_group 1;" ::: "memory");
        __syncthreads();

        const unsigned aBase = sA32 + (unsigned)(t % 3) * STG;
        const unsigned bBase = sB32 + (unsigned)(t % 3) * STG;
        unsigned a[4][2][4], b[4][4];
#pragma unroll
        for (int mi = 0; mi < 4; ++mi) {
            ldsm_x4(a[mi][0], aBase + aoff[mi]);
            ldsm_x4(a[mi][1], aBase + aoff[mi] + 32);
        }
#pragma unroll
        for (int ni = 0; ni < 4; ++ni)
            ldsm_x4(b[ni], bBase + boff[ni]);

#pragma unroll
        for (int s = 0; s < 2; ++s)
#pragma unroll
            for (int mi = 0; mi < 4; ++mi)
#pragma unroll
                for (int ni = 0; ni < 4; ++ni)
                    MMA_TF32(acc[mi][ni],
                             a[mi][s][0], a[mi][s][1], a[mi][s][2], a[mi][s][3],
                             b[ni][2 * s], b[ni][2 * s + 1]);

        const int tn = t + 2;
        if (tn < T) LOAD128(tn, tn % 3);
        asm volatile("cp.async.commit_group;" ::: "memory");
    }
#undef LOAD128

#pragma unroll
    for (int mi = 0; mi < 4; ++mi) {
        const int row = m0 + wm * 64 + mi * 16 + grp;
#pragma unroll
        for (int ni = 0; ni < 4; ++ni) {
            const int col = n0 + wn * 32 + ni * 8 + (qid << 1);
            const float2 bb = *(const float2*)(bias + col);
            float2 v0, v1;
            v0.x = acc[mi][ni][0] + bb.x; v0.y = acc[mi][ni][1] + bb.y;
            v1.x = acc[mi][ni][2] + bb.x; v1.y = acc[mi][ni][3] + bb.y;
            if (ACT) {
                v0.x = fmaxf(v0.x, 0.f); v0.y = fmaxf(v0.y, 0.f);
                v1.x = fmaxf(v1.x, 0.f); v1.y = fmaxf(v1.y, 0.f);
            }
            *(float2*)(C + (size_t)row * N + col) = v0;
            *(float2*)(C + (size_t)(row + 8) * N + col) = v1;
        }
    }
}

// ---------------- tf32 GEMM, 64x64 tiles, 256 thr, 4-stage, ldmatrix --------
template <int ACT>
__global__ void __launch_bounds__(256) tf32_gemm64_kernel(
    const float* __restrict__ A, const float* __restrict__ W,
    const float* __restrict__ bias, float* __restrict__ C,
    int K, int N) {
    __shared__ __align__(16) float sA[4][64 * 20];
    __shared__ __align__(16) float sB[4][64 * 20];

    const int tid = threadIdx.x;
    const int m0 = blockIdx.y << 6;
    const int n0 = blockIdx.x << 6;
    const int warp = tid >> 5, lane = tid & 31;
    const int wm = warp >> 2, wn = warp & 3;      // 2 x 4 warp grid
    const int grp = lane >> 2, qid = lane & 3;
    const int srow = tid >> 2;            // 0..63
    const int scol = (tid & 3) << 2;      // 0,4,8,12

    const unsigned sA32 = (unsigned)__cvta_generic_to_shared(&sA[0][0]);
    const unsigned sB32 = (unsigned)__cvta_generic_to_shared(&sB[0][0]);
    const unsigned STG = 64 * 20 * 4;

    unsigned aoff[2], boff[2];
#pragma unroll
    for (int mi = 0; mi < 2; ++mi)
        aoff[mi] = (unsigned)((wm * 32 + mi * 16 + ((lane >> 3) & 1) * 8 +
                               (lane & 7)) * 80 + ((lane >> 4) << 4));
#pragma unroll
    for (int ni = 0; ni < 2; ++ni)
        boff[ni] = (unsigned)((wn * 16 + ni * 8 + (lane & 7)) * 80 +
                              ((lane >> 3) << 4));

    const float* Abase = A + (size_t)m0 * K;
    const float* Bbase = W + (size_t)n0 * K;

    float acc[2][2][4];
#pragma unroll
    for (int mi = 0; mi < 2; ++mi)
#pragma unroll
        for (int ni = 0; ni < 2; ++ni)
#pragma unroll
            for (int r = 0; r < 4; ++r) acc[mi][ni][r] = 0.f;

#define LOAD64(t, buf)                                                       \
    do {                                                                     \
        const float* Ab = Abase + (size_t)(t) * 16;                          \
        const float* Bb = Bbase + (size_t)(t) * 16;                          \
        cp_async16(&sA[buf][srow * 20 + scol], Ab + (size_t)srow * K + scol);\
        cp_async16(&sB[buf][srow * 20 + scol], Bb + (size_t)srow * K + scol);\
    } while (0)

    const int T = K >> 4;
    LOAD64(0, 0);
    asm volatile("cp.async.commit_group;" ::: "memory");
    LOAD64(1, 1);
    asm volatile("cp.async.commit_group;" ::: "memory");
    LOAD64(2, 2);
    asm volatile("cp.async.commit_group;" ::: "memory");

    for (int t = 0; t < T; ++t) {
        asm volatile("cp.async.wait_group 2;" ::: "memory");
        __syncthreads();

        const unsigned aBase = sA32 + (unsigned)(t & 3) * STG;
        const unsigned bBase = sB32 + (unsigned)(t & 3) * STG;
        unsigned a[2][2][4], b[2][4];
#pragma unroll
        for (int mi = 0; mi < 2; ++mi) {
            ldsm_x4(a[mi][0], aBase + aoff[mi]);
            ldsm_x4(a[mi][1], aBase + aoff[mi] + 32);
        }
#pragma unroll
        for (int ni = 0; ni < 2; ++ni)
            ldsm_x4(b[ni], bBase + boff[ni]);

#pragma unroll
        for (int s = 0; s < 2; ++s)
#pragma unroll
            for (int mi = 0; mi < 2; ++mi)
#pragma unroll
                for (int ni = 0; ni < 2; ++ni)
                    MMA_TF32(acc[mi][ni],
                             a[mi][s][0], a[mi][s][1], a[mi][s][2], a[mi][s][3],
                             b[ni][2 * s], b[ni][2 * s + 1]);

        const int tn = t + 3;
        if (tn < T) LOAD64(tn, tn & 3);
        asm volatile("cp.async.commit_group;" ::: "memory");
    }
#undef LOAD64

#pragma unroll
    for (int mi = 0; mi < 2; ++mi) {
        const int row = m0 + wm * 32 + mi * 16 + grp;
#pragma unroll
        for (int ni = 0; ni < 2; ++ni) {
            const int col = n0 + wn * 16 + ni * 8 + (qid << 1);
            const float2 bb = *(const float2*)(bias + col);
            float2 v0, v1;
            v0.x = acc[mi][ni][0] + bb.x; v0.y = acc[mi][ni][1] + bb.y;
            v1.x = acc[mi][ni][2] + bb.x; v1.y = acc[mi][ni][3] + bb.y;
            if (ACT) {
                v0.x = fmaxf(v0.x, 0.f); v0.y = fmaxf(v0.y, 0.f);
                v1.x = fmaxf(v1.x, 0.f); v1.y = fmaxf(v1.y, 0.f);
            }
            *(float2*)(C + (size_t)row * N + col) = v0;
            *(float2*)(C + (size_t)(row + 8) * N + col) = v1;
        }
    }
}

// ---------------- fused MHA attention, split-K (streaming softmax, f32x2) ---
__global__ void __launch_bounds__(128) mha_attn_kernel(
    const float* __restrict__ QK, const float* __restrict__ V,
    float* __restrict__ O) {
    const int b = blockIdx.z, h = blockIdx.y;
    const int q0 = blockIdx.x << 6;
    const int tq = threadIdx.x & 63;
    const int kh = threadIdx.x >> 6;   // 0 or 1

    __shared__ __align__(16) float sK[2][64][36];
    __shared__ __align__(16) float sV[2][64][36];

    const float scale = 0.17677669529663687f;  // 1/sqrt(32)
    u64 q2[16], o2[16];
    const float* qrow = QK + (size_t)(b * LQn + q0 + tq) * 512 + h * 32;
#pragma unroll
    for (int i = 0; i < 8; ++i) {
        float4 v4 = *(const float4*)(qrow + i * 4);
        q2[2 * i]     = f2pack(v4.x * scale, v4.y * scale);
        q2[2 * i + 1] = f2pack(v4.z * scale, v4.w * scale);
        o2[2 * i] = 0ull; o2[2 * i + 1] = 0ull;
    }
    float m = -1e30f, l = 0.f;

    const int ktEnd = (kh + 1) * (LQn / 128);
#pragma unroll 1
    for (int kt = kh * (LQn / 128); kt < ktEnd; ++kt) {
        const int krow = (kt << 6) + tq;
        const float* kr = QK + (size_t)(b * LQn + krow) * 512 + 256 + h * 32;
        const float* vr = V + (size_t)(b * LQn + krow) * 256 + h * 32;
#pragma unroll
        for (int d = 0; d < 32; d += 4) {
            *(float4*)&sK[kh][tq][d] = *(const float4*)(kr + d);
            *(float4*)&sV[kh][tq][d] = *(const float4*)(vr + d);
        }
        __syncthreads();

#pragma unroll 1
        for (int j0 = 0; j0 < 64; j0 += 8) {
            float s[8];
#pragma unroll
            for (int jj = 0; jj < 8; ++jj) {
                const ulonglong2* kp = (const ulonglong2*)&sK[kh][j0 + jj][0];
                u64 a0 = 0ull, a1 = 0ull;
#pragma unroll
                for (int i = 0; i < 8; ++i) {
                    ulonglong2 kk = kp[i];
                    a0 = f2fma(q2[2 * i], kk.x, a0);
                    a1 = f2fma(q2[2 * i + 1], kk.y, a1);
                }
                const float2 p0 = f2unpack(a0), p1 = f2unpack(a1);
                s[jj] = (p0.x + p0.y) + (p1.x + p1.y);
            }
            float mx = m;
#pragma unroll
            for (int jj = 0; jj < 8; ++jj) mx = fmaxf(mx, s[jj]);
            const float corr = __expf(m - mx);
            m = mx;
            l *= corr;
            const u64 c2 = f2pack(corr, corr);
#pragma unroll
            for (int i = 0; i < 16; ++i) o2[i] = f2mul(o2[i], c2);
#pragma unroll
            for (int jj = 0; jj < 8; ++jj) {
                const float e = __expf(s[jj] - m);
                l += e;
                const u64 e2 = f2pack(e, e);
                const ulonglong2* vp = (const ulonglong2*)&sV[kh][j0 + jj][0];
#pragma unroll
                for (int i = 0; i < 8; ++i) {
                    ulonglong2 vv = vp[i];
                    o2[2 * i]     = f2fma(e2, vv.x, o2[2 * i]);
                    o2[2 * i + 1] = f2fma(e2, vv.y, o2[2 * i + 1]);
                }
            }
        }
        __syncthreads();
    }

    // ---- merge the two key-half partials ----
    if (kh == 1) {
        sK[0][tq][0] = m;
        sK[0][tq][1] = l;
#pragma unroll
        for (int i = 0; i < 16; ++i)
            *(u64*)&sV[1][tq][2 * i] = o2[i];
    }
    __syncthreads();
    if (kh == 0) {
        const float m1 = sK[0][tq][0];
        const float l1 = sK[0][tq][1];
        const float M = fmaxf(m, m1);
        const float c0 = __expf(m - M);
        const float c1 = __expf(m1 - M);
        const float L = l * c0 + l1 * c1;
        const float inv = 1.f / L;
        const u64 c02 = f2pack(c0 * inv, c0 * inv);
        const u64 c12 = f2pack(c1 * inv, c1 * inv);
        float* orow = O + (size_t)(b * LQn + q0 + tq) * 256 + h * 32;
#pragma unroll
        for (int i = 0; i < 8; ++i) {
            u64 r0 = f2mul(o2[2 * i], c02);
            u64 r1 = f2mul(o2[2 * i + 1], c02);
            r0 = f2fma(*(const u64*)&sV[1][tq][4 * i], c12, r0);
            r1 = f2fma(*(const u64*)&sV[1][tq][4 * i + 2], c12, r1);
            const float2 a = f2unpack(r0);
            const float2 c = f2unpack(r1);
            float4 v4;
            v4.x = a.x; v4.y = a.y; v4.z = c.x; v4.w = c.y;
            *(float4*)(orow + i * 4) = v4;
        }
    }
}

// ---------------- residual add + LayerNorm (+ optional pos-added copy) ------
template <int WPOS>
__global__ void __launch_bounds__(256) add_ln_kernel(
    const float* __restrict__ X, const float* __restrict__ R,
    const float* __restrict__ g, const float* __restrict__ bb,
    float* __restrict__ out,
    const float* __restrict__ pos, float* __restrict__ out2) {
    const int r = blockIdx.x, t = threadIdx.x;
    const float v = X[(size_t)r * CC + t] + R[(size_t)r * CC + t];
    float s = v, s2 = v * v;
#pragma unroll
    for (int off = 16; off; off >>= 1) {
        s  += __shfl_xor_sync(0xffffffffu, s,  off);
        s2 += __shfl_xor_sync(0xffffffffu, s2, off);
    }
    __shared__ float sh[8], sh2[8];
    const int w = t >> 5, ln = t & 31;
    if (ln == 0) { sh[w] = s; sh2[w] = s2; }
    __syncthreads();
    if (t == 0) {
        float a = 0.f, b2 = 0.f;
#pragma unroll
        for (int i = 0; i < 8; ++i) { a += sh[i]; b2 += sh2[i]; }
        const float mean = a * (1.f / 256.f);
        const float var = b2 * (1.f / 256.f) - mean * mean;
        sh[0] = mean;
        sh2[0] = rsqrtf(var + 1e-5f);
    }
    __syncthreads();
    const float mean = sh[0], inv = sh2[0];
    const float y = (v - mean) * inv * g[t] + bb[t];
    out[(size_t)r * CC + t] = y;
    if (WPOS)
        out2[(size_t)r * CC + t] = y + pos[(size_t)r * CC + t];
}

// ---------------- MS deformable sampling (fused off|aw layout, stride 384) ---
__global__ void __launch_bounds__(256) deform_kernel(
    const float* __restrict__ value,   // [B*LSRC, 256]
    const float* __restrict__ offaw,   // [M1, 384]: cols 0..255 off, 256..383 aw
    const float* __restrict__ refp,    // [B, LQ, L, 2]
    float* __restrict__ out) {         // [M1, 256]
    const int wid = blockIdx.x * 8 + (threadIdx.x >> 5);
    const int lane = threadIdx.x & 31;
    const int h = wid & 7;
    const int q = (wid >> 3) & 1023;
    const int b = wid >> 13;

    const float* rowp = offaw + (size_t)(b * LQn + q) * 384;
    const float* ar = rowp + 256 + h * 16;
    const float logit = (lane < 16) ? ar[lane] : -1e30f;
    float mx = logit;
#pragma unroll
    for (int o = 16; o; o >>= 1)
        mx = fmaxf(mx, __shfl_xor_sync(0xffffffffu, mx, o));
    float e = (lane < 16) ? __expf(logit - mx) : 0.f;
    float se = e;
#pragma unroll
    for (int o = 16; o; o >>= 1) se += __shfl_xor_sync(0xffffffffu, se, o);
    const float p = e / se;

    const int   SZ[4] = {128, 64, 32, 16};
    const int   ST[4] = {0, 16384, 20480, 21504};
    const float* offr = rowp + h * 32;
    const float* refr = refp + (size_t)(b * LQn + q) * 8;

    float acc = 0.f;
#pragma unroll
    for (int l = 0; l < 4; ++l) {
        const int Wl = SZ[l];
        const float Wf = (float)Wl;
        const float rx = refr[l * 2 + 0];
        const float ry = refr[l * 2 + 1];
        const float* vb =
            value + ((size_t)b * LSRC + ST[l]) * 256 + h * 32 + lane;
#pragma unroll
        for (int pt = 0; pt < 4; ++pt) {
            const float ox = offr[(l * 4 + pt) * 2 + 0];
            const float oy = offr[(l * 4 + pt) * 2 + 1];
            const float x = (rx + ox / Wf) * Wf - 0.5f;
            const float y = (ry + oy / Wf) * Wf - 0.5f;
            const float x0f = floorf(x), y0f = floorf(y);
            const int x0 = (int)x0f, y0 = (int)y0f;
            const float wx1 = x - x0f, wx0 = 1.f - wx1;
            const float wy1 = y - y0f, wy0 = 1.f - wy1;
            const float aw = __shfl_sync(0xffffffffu, p, l * 4 + pt);

            if ((unsigned)x0 < (unsigned)Wl && (unsigned)y0 < (unsigned)Wl)
                acc = fmaf(aw * (wx0 * wy0),
                           vb[((size_t)y0 * Wl + x0) * 256], acc);
            if ((unsigned)(x0 + 1) < (unsigned)Wl && (unsigned)y0 < (unsigned)Wl)
                acc = fmaf(aw * (wx1 * wy0),
                           vb[((size_t)y0 * Wl + x0 + 1) * 256], acc);
            if ((unsigned)x0 < (unsigned)Wl && (unsigned)(y0 + 1) < (unsigned)Wl)
                acc = fmaf(aw * (wx0 * wy1),
                           vb[((size_t)(y0 + 1) * Wl + x0) * 256], acc);
            if ((unsigned)(x0 + 1) < (unsigned)Wl &&
                (unsigned)(y0 + 1) < (unsigned)Wl)
                acc = fmaf(aw * (wx1 * wy1),
                           vb[((size_t)(y0 + 1) * Wl + x0 + 1) * 256], acc);
        }
    }
    out[(size_t)(b * LQn + q) * 256 + h * 32 + lane] = acc;
}

// ---------------- launch (serial, single stream) -----------------------------
extern "C" void kernel_launch(void* const* d_in, const int* in_sizes, int n_in,
                              void* d_out, int out_size) {
    const float* tgt   = (const float*)d_in[0];
    const float* qpos  = (const float*)d_in[1];
    const float* refp  = (const float*)d_in[2];
    const float* src   = (const float*)d_in[3];
    const float* in_w  = (const float*)d_in[4];
    const float* in_b  = (const float*)d_in[5];
    const float* sa_w  = (const float*)d_in[6];
    const float* sa_b  = (const float*)d_in[7];
    const float* off_w = (const float*)d_in[8];
    const float* off_b = (const float*)d_in[9];
    const float* aw_w  = (const float*)d_in[10];
    const float* aw_b  = (const float*)d_in[11];
    const float* val_w = (const float*)d_in[12];
    const float* val_b = (const float*)d_in[13];
    const float* co_w  = (const float*)d_in[14];
    const float* co_b  = (const float*)d_in[15];
    const float* ln1_g = (const float*)d_in[16];
    const float* ln1_b = (const float*)d_in[17];
    const float* ln2_g = (const float*)d_in[18];
    const float* ln2_b = (const float*)d_in[19];
    const float* ln3_g = (const float*)d_in[20];
    const float* ln3_b = (const float*)d_in[21];
    const float* f1_w  = (const float*)d_in[22];
    const float* f1_b  = (const float*)d_in[23];
    const float* f2_w  = (const float*)d_in[24];
    const float* f2_b  = (const float*)d_in[25];
    float* out = (float*)d_out;

    float* s = nullptr;
    cudaGetSymbolAddress((void**)&s, g_scratch);
    float* qk    = s + OF_QK;
    float* qkp   = s + OF_QKP;
    float* vbuf  = s + OF_V;
    float* attn  = s + OF_ATT;
    float* tgta  = s + OF_TGA;
    float* q2    = s + OF_Q2;
    float* value = s + OF_VAL;
    float* dfo   = s + OF_DFO;
    float* offaw = s + OF_OFW;
    float* tmp   = s + OF_TMP;
    float* tgtb  = s + OF_TGB;
    float* ffh   = s + OF_FFH;
    float* wcat  = s + OF_WCT;
    float* bcat  = s + OF_BCT;

    const int n4 = M1 * CC / 4;

    // concat off|aw weights (D2D memcpy nodes, ~0.4 MB)
    cudaMemcpyAsync(wcat, off_w, (size_t)256 * CC * sizeof(float),
                    cudaMemcpyDeviceToDevice, 0);
    cudaMemcpyAsync(wcat + 256 * CC, aw_w, (size_t)128 * CC * sizeof(float),
                    cudaMemcpyDeviceToDevice, 0);
    cudaMemcpyAsync(bcat, off_b, 256 * sizeof(float),
                    cudaMemcpyDeviceToDevice, 0);
    cudaMemcpyAsync(bcat + 256, aw_b, 128 * sizeof(float),
                    cudaMemcpyDeviceToDevice, 0);

    // --- self-attention block ---
    add_vec_kernel<<<(n4 + 255) / 256, 256>>>(
        (const float4*)tgt, (const float4*)qpos, (float4*)qk, n4);      // 0
    tf32_gemm64_kernel<0><<<dim3(512 / 64, M1 / 64), 256>>>(
        qk, in_w, in_b, qkp, CC, 512);                                  // 1
    tf32_gemm64_kernel<0><<<dim3(CC / 64, M1 / 64), 256>>>(
        tgt, in_w + 512 * CC, in_b + 512, vbuf, CC, CC);                // 2
    mha_attn_kernel<<<dim3(LQn / 64, HH, BQ), 128>>>(qkp, vbuf, attn);  // 3
    tf32_gemm64_kernel<0><<<dim3(CC / 64, M1 / 64), 256>>>(
        attn, sa_w, sa_b, tmp, CC, CC);                                 // 4
    add_ln_kernel<1><<<M1, 256>>>(tmp, tgt, ln2_g, ln2_b, tgta,
                                  qpos, q2);                            // 5

    // value projection at kernel index 6 (profiled slot)
    tf32_gemm_kernel<0><<<dim3(CC / 128, MS / 128), 256>>>(
        src, val_w, val_b, value, CC, CC);                              // 6

    // --- deformable cross-attention block ---
    tf32_gemm64_kernel<0><<<dim3(384 / 64, M1 / 64), 256>>>(
        q2, wcat, bcat, offaw, CC, 384);                                // 7
    deform_kernel<<<(BQ * LQn * HH) / 8, 256>>>(value, offaw, refp, dfo); // 8
    tf32_gemm64_kernel<0><<<dim3(CC / 64, M1 / 64), 256>>>(
        dfo, co_w, co_b, tmp, CC, CC);                                  // 9
    add_ln_kernel<0><<<M1, 256>>>(tmp, tgta, ln1_g, ln1_b, tgtb,
                                  nullptr, nullptr);                    // 10

    // --- FFN block ---
    tf32_gemm_kernel<1><<<dim3(DFFn / 128, M1 / 128), 256>>>(
        tgtb, f1_w, f1_b, ffh, CC, DFFn);                               // 11
    tf32_gemm64_kernel<0><<<dim3(CC / 64, M1 / 64), 256>>>(
        ffh, f2_w, f2_b, tmp, DFFn, CC);                                // 12
    add_ln_kernel<0><<<M1, 256>>>(tmp, tgtb, ln3_g, ln3_b, out,
                                  nullptr, nullptr);                    // 13
}

// round 16
// speedup vs baseline: 1.3930x; 1.3674x over previous
#include <cuda_runtime.h>
#include <math.h>
#include <stdint.h>

// ---------------- problem constants ----------------
#define BQ   4
#define LQn  1024
#define CC   256
#define HH   8
#define DFFn 1024
#define LSRC 21760
#define M1   (BQ * LQn)     // 4096 query rows
#define MS   (BQ * LSRC)    // 87040 source rows

typedef unsigned long long u64;

// ---------------- scratch (static device global, no allocs) ----------------
static constexpr size_t OF_QK  = 0;
static constexpr size_t OF_QKP = OF_QK  + (size_t)M1 * CC;      // Q|K packed, 512 cols
static constexpr size_t OF_V   = OF_QKP + (size_t)M1 * 512;
static constexpr size_t OF_ATT = OF_V   + (size_t)M1 * CC;
static constexpr size_t OF_TGA = OF_ATT + (size_t)M1 * CC;
static constexpr size_t OF_Q2  = OF_TGA + (size_t)M1 * CC;
static constexpr size_t OF_VAL = OF_Q2  + (size_t)M1 * CC;
static constexpr size_t OF_DFO = OF_VAL + (size_t)MS * CC;
static constexpr size_t OF_OFW = OF_DFO + (size_t)M1 * CC;      // off|aw out, stride 384
static constexpr size_t OF_TMP = OF_OFW + (size_t)M1 * 384;
static constexpr size_t OF_TGB = OF_TMP + (size_t)M1 * CC;
static constexpr size_t OF_FFH = OF_TGB + (size_t)M1 * CC;
static constexpr size_t OF_WCT = OF_FFH + (size_t)M1 * DFFn;    // concat off_w|aw_w [384,256]
static constexpr size_t OF_BCT = OF_WCT + (size_t)384 * CC;     // concat bias [384]
static constexpr size_t SCRATCH_TOTAL = OF_BCT + 384;

__device__ __align__(16) float g_scratch[SCRATCH_TOTAL];

// ---------------- small helpers ----------------
__device__ __forceinline__ void cp_async16(void* s, const void* g) {
    unsigned sa = (unsigned)__cvta_generic_to_shared(s);
    asm volatile("cp.async.ca.shared.global [%0], [%1], 16;" :: "r"(sa), "l"(g));
}
__device__ __forceinline__ void ldsm_x4(unsigned* r, unsigned addr) {
    asm volatile(
        "ldmatrix.sync.aligned.m8n8.x4.shared.b16 {%0,%1,%2,%3}, [%4];"
        : "=r"(r[0]), "=r"(r[1]), "=r"(r[2]), "=r"(r[3]) : "r"(addr));
}
#define MMA_TF32(accp, a0, a1, a2, a3, b0, b1)                               \
    asm volatile(                                                            \
        "mma.sync.aligned.m16n8k8.row.col.f32.tf32.tf32.f32 "                \
        "{%0,%1,%2,%3}, {%4,%5,%6,%7}, {%8,%9}, {%0,%1,%2,%3};"              \
        : "+f"((accp)[0]), "+f"((accp)[1]), "+f"((accp)[2]), "+f"((accp)[3]) \
        : "r"(a0), "r"(a1), "r"(a2), "r"(a3), "r"(b0), "r"(b1))

// ---------------- elementwise add (float4) ----------------
__global__ void add_vec_kernel(const float4* __restrict__ a,
                               const float4* __restrict__ b,
                               float4* __restrict__ o, int n4) {
    int i = blockIdx.x * blockDim.x + threadIdx.x;
    if (i < n4) {
        float4 x = a[i], y = b[i];
        o[i] = make_float4(x.x + y.x, x.y + y.y, x.z + y.z, x.w + y.w);
    }
}

// ---------------- tf32 GEMM, 128x128 tiles, 3-stage, ldmatrix ---------------
template <int ACT>
__global__ void __launch_bounds__(256, 2) tf32_gemm_kernel(
    const float* __restrict__ A, const float* __restrict__ W,
    const float* __restrict__ bias, float* __restrict__ C,
    int K, int N) {
    __shared__ __align__(16) float sA[3][128 * 20];
    __shared__ __align__(16) float sB[3][128 * 20];

    const int tid = threadIdx.x;
    const int m0 = blockIdx.y << 7;
    const int n0 = blockIdx.x << 7;
    const int warp = tid >> 5, lane = tid & 31;
    const int wm = warp >> 2, wn = warp & 3;
    const int grp = lane >> 2, qid = lane & 3;

    const unsigned sA32 = (unsigned)__cvta_generic_to_shared(&sA[0][0]);
    const unsigned sB32 = (unsigned)__cvta_generic_to_shared(&sB[0][0]);
    const unsigned STG = 128 * 20 * 4;

    unsigned aoff[4], boff[4];
#pragma unroll
    for (int mi = 0; mi < 4; ++mi)
        aoff[mi] = (unsigned)((wm * 64 + mi * 16 + ((lane >> 3) & 1) * 8 +
                               (lane & 7)) * 80 + ((lane >> 4) << 4));
#pragma unroll
    for (int ni = 0; ni < 4; ++ni)
        boff[ni] = (unsigned)((wn * 32 + ni * 8 + (lane & 7)) * 80 +
                              ((lane >> 3) << 4));

    float acc[4][4][4];
#pragma unroll
    for (int mi = 0; mi < 4; ++mi)
#pragma unroll
        for (int ni = 0; ni < 4; ++ni)
#pragma unroll
            for (int r = 0; r < 4; ++r) acc[mi][ni][r] = 0.f;

    const int srow = tid >> 2;
    const int scol = (tid & 3) << 2;
    const float* Abase = A + (size_t)m0 * K;
    const float* Bbase = W + (size_t)n0 * K;

#define LOAD128(t, buf)                                                     \
    do {                                                                    \
        const float* Ab = Abase + (size_t)(t) * 16;                         \
        const float* Bb = Bbase + (size_t)(t) * 16;                         \
        _Pragma("unroll")                                                   \
        for (int i = 0; i < 2; ++i) {                                       \
            int row = i * 64 + srow;                                        \
            cp_async16(&sA[buf][row * 20 + scol], Ab + (size_t)row * K + scol); \
            cp_async16(&sB[buf][row * 20 + scol], Bb + (size_t)row * K + scol); \
        }                                                                   \
    } while (0)

    const int T = K >> 4;
    LOAD128(0, 0);
    asm volatile("cp.async.commit_group;" ::: "memory");
    LOAD128(1, 1);
    asm volatile("cp.async.commit_group;" ::: "memory");

    for (int t = 0; t < T; ++t) {
        asm volatile("cp.async.wait_group 1;" ::: "memory");
        __syncthreads();

        const unsigned aBase = sA32 + (unsigned)(t % 3) * STG;
        const unsigned bBase = sB32 + (unsigned)(t % 3) * STG;
        unsigned a[4][2][4], b[4][4];
#pragma unroll
        for (int mi = 0; mi < 4; ++mi) {
            ldsm_x4(a[mi][0], aBase + aoff[mi]);
            ldsm_x4(a[mi][1], aBase + aoff[mi] + 32);
        }
#pragma unroll
        for (int ni = 0; ni < 4; ++ni)
            ldsm_x4(b[ni], bBase + boff[ni]);

#pragma unroll
        for (int s = 0; s < 2; ++s)
#pragma unroll
            for (int mi = 0; mi < 4; ++mi)
#pragma unroll
                for (int ni = 0; ni < 4; ++ni)
                    MMA_TF32(acc[mi][ni],
                             a[mi][s][0], a[mi][s][1], a[mi][s][2], a[mi][s][3],
                             b[ni][2 * s], b[ni][2 * s + 1]);

        const int tn = t + 2;
        if (tn < T) LOAD128(tn, tn % 3);
        asm volatile("cp.async.commit_group;" ::: "memory");
    }
#undef LOAD128

#pragma unroll
    for (int mi = 0; mi < 4; ++mi) {
        const int row = m0 + wm * 64 + mi * 16 + grp;
#pragma unroll
        for (int ni = 0; ni < 4; ++ni) {
            const int col = n0 + wn * 32 + ni * 8 + (qid << 1);
            const float2 bb = *(const float2*)(bias + col);
            float2 v0, v1;
            v0.x = acc[mi][ni][0] + bb.x; v0.y = acc[mi][ni][1] + bb.y;
            v1.x = acc[mi][ni][2] + bb.x; v1.y = acc[mi][ni][3] + bb.y;
            if (ACT) {
                v0.x = fmaxf(v0.x, 0.f); v0.y = fmaxf(v0.y, 0.f);
                v1.x = fmaxf(v1.x, 0.f); v1.y = fmaxf(v1.y, 0.f);
            }
            *(float2*)(C + (size_t)row * N + col) = v0;
            *(float2*)(C + (size_t)(row + 8) * N + col) = v1;
        }
    }
}

// ---------------- tf32 GEMM, 64x64 tiles, 256 thr, 4-stage, ldmatrix --------
template <int ACT>
__global__ void __launch_bounds__(256) tf32_gemm64_kernel(
    const float* __restrict__ A, const float* __restrict__ W,
    const float* __restrict__ bias, float* __restrict__ C,
    int K, int N) {
    __shared__ __align__(16) float sA[4][64 * 20];
    __shared__ __align__(16) float sB[4][64 * 20];

    const int tid = threadIdx.x;
    const int m0 = blockIdx.y << 6;
    const int n0 = blockIdx.x << 6;
    const int warp = tid >> 5, lane = tid & 31;
    const int wm = warp >> 2, wn = warp & 3;
    const int grp = lane >> 2, qid = lane & 3;
    const int srow = tid >> 2;
    const int scol = (tid & 3) << 2;

    const unsigned sA32 = (unsigned)__cvta_generic_to_shared(&sA[0][0]);
    const unsigned sB32 = (unsigned)__cvta_generic_to_shared(&sB[0][0]);
    const unsigned STG = 64 * 20 * 4;

    unsigned aoff[2], boff[2];
#pragma unroll
    for (int mi = 0; mi < 2; ++mi)
        aoff[mi] = (unsigned)((wm * 32 + mi * 16 + ((lane >> 3) & 1) * 8 +
                               (lane & 7)) * 80 + ((lane >> 4) << 4));
#pragma unroll
    for (int ni = 0; ni < 2; ++ni)
        boff[ni] = (unsigned)((wn * 16 + ni * 8 + (lane & 7)) * 80 +
                              ((lane >> 3) << 4));

    const float* Abase = A + (size_t)m0 * K;
    const float* Bbase = W + (size_t)n0 * K;

    float acc[2][2][4];
#pragma unroll
    for (int mi = 0; mi < 2; ++mi)
#pragma unroll
        for (int ni = 0; ni < 2; ++ni)
#pragma unroll
            for (int r = 0; r < 4; ++r) acc[mi][ni][r] = 0.f;

#define LOAD64(t, buf)                                                       \
    do {                                                                     \
        const float* Ab = Abase + (size_t)(t) * 16;                          \
        const float* Bb = Bbase + (size_t)(t) * 16;                          \
        cp_async16(&sA[buf][srow * 20 + scol], Ab + (size_t)srow * K + scol);\
        cp_async16(&sB[buf][srow * 20 + scol], Bb + (size_t)srow * K + scol);\
    } while (0)

    const int T = K >> 4;
    LOAD64(0, 0);
    asm volatile("cp.async.commit_group;" ::: "memory");
    LOAD64(1, 1);
    asm volatile("cp.async.commit_group;" ::: "memory");
    LOAD64(2, 2);
    asm volatile("cp.async.commit_group;" ::: "memory");

    for (int t = 0; t < T; ++t) {
        asm volatile("cp.async.wait_group 2;" ::: "memory");
        __syncthreads();

        const unsigned aBase = sA32 + (unsigned)(t & 3) * STG;
        const unsigned bBase = sB32 + (unsigned)(t & 3) * STG;
        unsigned a[2][2][4], b[2][4];
#pragma unroll
        for (int mi = 0; mi < 2; ++mi) {
            ldsm_x4(a[mi][0], aBase + aoff[mi]);
            ldsm_x4(a[mi][1], aBase + aoff[mi] + 32);
        }
#pragma unroll
        for (int ni = 0; ni < 2; ++ni)
            ldsm_x4(b[ni], bBase + boff[ni]);

#pragma unroll
        for (int s = 0; s < 2; ++s)
#pragma unroll
            for (int mi = 0; mi < 2; ++mi)
#pragma unroll
                for (int ni = 0; ni < 2; ++ni)
                    MMA_TF32(acc[mi][ni],
                             a[mi][s][0], a[mi][s][1], a[mi][s][2], a[mi][s][3],
                             b[ni][2 * s], b[ni][2 * s + 1]);

        const int tn = t + 3;
        if (tn < T) LOAD64(tn, tn & 3);
        asm volatile("cp.async.commit_group;" ::: "memory");
    }
#undef LOAD64

#pragma unroll
    for (int mi = 0; mi < 2; ++mi) {
        const int row = m0 + wm * 32 + mi * 16 + grp;
#pragma unroll
        for (int ni = 0; ni < 2; ++ni) {
            const int col = n0 + wn * 16 + ni * 8 + (qid << 1);
            const float2 bb = *(const float2*)(bias + col);
            float2 v0, v1;
            v0.x = acc[mi][ni][0] + bb.x; v0.y = acc[mi][ni][1] + bb.y;
            v1.x = acc[mi][ni][2] + bb.x; v1.y = acc[mi][ni][3] + bb.y;
            if (ACT) {
                v0.x = fmaxf(v0.x, 0.f); v0.y = fmaxf(v0.y, 0.f);
                v1.x = fmaxf(v1.x, 0.f); v1.y = fmaxf(v1.y, 0.f);
            }
            *(float2*)(C + (size_t)row * N + col) = v0;
            *(float2*)(C + (size_t)(row + 8) * N + col) = v1;
        }
    }
}

// ---------------- flash attention via mma.sync (tf32) -----------------------
// Block: 64 queries of one (b,h). 4 warps x 16 queries. 16 key-tiles of 64.
// QK: [M1,512] (Q cols h*32, K cols 256+h*32), V: [M1,256], out: [M1,256].
__global__ void __launch_bounds__(128) mha_attn_kernel(
    const float* __restrict__ QK, const float* __restrict__ V,
    float* __restrict__ Og) {
    __shared__ __align__(16) float sQ[64][36];
    __shared__ __align__(16) float sK[64][36];
    __shared__ __align__(16) float sV[64][36];
    __shared__ __align__(16) float sP[64][68];

    const int b = blockIdx.z, h = blockIdx.y;
    const int q0 = blockIdx.x << 6;
    const int tid = threadIdx.x;
    const int warp = tid >> 5, lane = tid & 31;
    const int grp = lane >> 2, qid = lane & 3;

    const unsigned sQ32 = (unsigned)__cvta_generic_to_shared(&sQ[0][0]);
    const unsigned sK32 = (unsigned)__cvta_generic_to_shared(&sK[0][0]);
    const unsigned sP32 = (unsigned)__cvta_generic_to_shared(&sP[0][0]);

    // ---- load Q tile (64x32) ----
    {
        const int r = tid >> 1;
        const int c = (tid & 1) << 4;
        const float* g = QK + (size_t)(b * LQn + q0 + r) * 512 + h * 32 + c;
        cp_async16(&sQ[r][c], g);
        cp_async16(&sQ[r][c + 4], g + 4);
        cp_async16(&sQ[r][c + 8], g + 8);
        cp_async16(&sQ[r][c + 12], g + 12);
    }
    asm volatile("cp.async.commit_group;" ::: "memory");
    asm volatile("cp.async.wait_group 0;" ::: "memory");
    __syncthreads();

    // ---- Q fragments (4 ksteps), pre-scaled by 1/sqrt(32) ----
    const float scale = 0.17677669529663687f;
    unsigned qf[4][4];
    {
        const unsigned base = sQ32 +
            (unsigned)((warp * 16 + ((lane >> 3) & 1) * 8 + (lane & 7)) * 144 +
                       ((lane >> 4) << 4));
#pragma unroll
        for (int ks = 0; ks < 4; ++ks) {
            ldsm_x4(qf[ks], base + ks * 32);
#pragma unroll
            for (int j = 0; j < 4; ++j)
                qf[ks][j] = __float_as_uint(__uint_as_float(qf[ks][j]) * scale);
        }
    }

    float o[4][4];
#pragma unroll
    for (int n = 0; n < 4; ++n)
#pragma unroll
        for (int j = 0; j < 4; ++j) o[n][j] = 0.f;
    float m0 = -1e30f, m1 = -1e30f, l0 = 0.f, l1 = 0.f;

    const unsigned kfoff = (unsigned)(((lane & 7)) * 144 + ((lane >> 3) << 4));
    const unsigned pfoff = (unsigned)((warp * 16 + ((lane >> 3) & 1) * 8 +
                                      (lane & 7)) * 272 + ((lane >> 4) << 4));

#pragma unroll 1
    for (int kt = 0; kt < 16; ++kt) {
        // load K,V tiles (64x32 each)
        {
            const int r = tid >> 1;
            const int c = (tid & 1) << 4;
            const size_t row = (size_t)(b * LQn + kt * 64 + r);
            const float* gk = QK + row * 512 + 256 + h * 32 + c;
            const float* gv = V + row * 256 + h * 32 + c;
            cp_async16(&sK[r][c], gk);
            cp_async16(&sK[r][c + 4], gk + 4);
            cp_async16(&sK[r][c + 8], gk + 8);
            cp_async16(&sK[r][c + 12], gk + 12);
            cp_async16(&sV[r][c], gv);
            cp_async16(&sV[r][c + 4], gv + 4);
            cp_async16(&sV[r][c + 8], gv + 8);
            cp_async16(&sV[r][c + 12], gv + 12);
        }
        asm volatile("cp.async.commit_group;" ::: "memory");
        asm volatile("cp.async.wait_group 0;" ::: "memory");
        __syncthreads();

        // ---- S = Q @ K^T : 8 ntiles x 64 keys ----
        float sc[8][4];
#pragma unroll
        for (int nt = 0; nt < 8; ++nt)
#pragma unroll
            for (int j = 0; j < 4; ++j) sc[nt][j] = 0.f;
#pragma unroll
        for (int s = 0; s < 2; ++s) {
            unsigned bf[8][4];
#pragma unroll
            for (int nt = 0; nt < 8; ++nt)
                ldsm_x4(bf[nt], sK32 + kfoff + (unsigned)(nt * 8 * 144 + s * 64));
#pragma unroll
            for (int nt = 0; nt < 8; ++nt) {
                MMA_TF32(sc[nt], qf[2 * s][0], qf[2 * s][1], qf[2 * s][2],
                         qf[2 * s][3], bf[nt][0], bf[nt][1]);
                MMA_TF32(sc[nt], qf[2 * s + 1][0], qf[2 * s + 1][1],
                         qf[2 * s + 1][2], qf[2 * s + 1][3],
                         bf[nt][2], bf[nt][3]);
            }
        }

        // ---- online softmax (rows grp, grp+8) ----
        float r0 = -1e30f, r1 = -1e30f;
#pragma unroll
        for (int nt = 0; nt < 8; ++nt) {
            r0 = fmaxf(r0, fmaxf(sc[nt][0], sc[nt][1]));
            r1 = fmaxf(r1, fmaxf(sc[nt][2], sc[nt][3]));
        }
        r0 = fmaxf(r0, __shfl_xor_sync(0xffffffffu, r0, 1));
        r0 = fmaxf(r0, __shfl_xor_sync(0xffffffffu, r0, 2));
        r1 = fmaxf(r1, __shfl_xor_sync(0xffffffffu, r1, 1));
        r1 = fmaxf(r1, __shfl_xor_sync(0xffffffffu, r1, 2));
        const float mn0 = fmaxf(m0, r0), mn1 = fmaxf(m1, r1);
        const float c0 = __expf(m0 - mn0), c1 = __expf(m1 - mn1);
        m0 = mn0; m1 = mn1;
        float ps0 = 0.f, ps1 = 0.f;
#pragma unroll
        for (int nt = 0; nt < 8; ++nt) {
            sc[nt][0] = __expf(sc[nt][0] - m0); ps0 += sc[nt][0];
            sc[nt][1] = __expf(sc[nt][1] - m0); ps0 += sc[nt][1];
            sc[nt][2] = __expf(sc[nt][2] - m1); ps1 += sc[nt][2];
            sc[nt][3] = __expf(sc[nt][3] - m1); ps1 += sc[nt][3];
        }
        ps0 += __shfl_xor_sync(0xffffffffu, ps0, 1);
        ps0 += __shfl_xor_sync(0xffffffffu, ps0, 2);
        ps1 += __shfl_xor_sync(0xffffffffu, ps1, 1);
        ps1 += __shfl_xor_sync(0xffffffffu, ps1, 2);
        l0 = l0 * c0 + ps0;
        l1 = l1 * c1 + ps1;
#pragma unroll
        for (int n = 0; n < 4; ++n) {
            o[n][0] *= c0; o[n][1] *= c0;
            o[n][2] *= c1; o[n][3] *= c1;
        }

        // ---- store P to warp-private smem strip ----
        const int pr = warp * 16 + grp;
#pragma unroll
        for (int nt = 0; nt < 8; ++nt) {
            *(float2*)&sP[pr][nt * 8 + 2 * qid] =
                make_float2(sc[nt][0], sc[nt][1]);
            *(float2*)&sP[pr + 8][nt * 8 + 2 * qid] =
                make_float2(sc[nt][2], sc[nt][3]);
        }
        __syncwarp();

        // ---- O += P @ V ----
#pragma unroll
        for (int kk = 0; kk < 8; ++kk) {
            unsigned af[4];
            ldsm_x4(af, sP32 + pfoff + (unsigned)(kk * 32));
#pragma unroll
            for (int n = 0; n < 4; ++n) {
                const unsigned b0 =
                    __float_as_uint(sV[kk * 8 + qid][n * 8 + grp]);
                const unsigned b1 =
                    __float_as_uint(sV[kk * 8 + qid + 4][n * 8 + grp]);
                MMA_TF32(o[n], af[0], af[1], af[2], af[3], b0, b1);
            }
        }
        __syncthreads();
    }

    // ---- epilogue ----
    const float i0 = 1.f / l0, i1 = 1.f / l1;
    const int row = b * LQn + q0 + warp * 16 + grp;
    float* o0 = Og + (size_t)row * 256 + h * 32;
    float* o1 = Og + (size_t)(row + 8) * 256 + h * 32;
#pragma unroll
    for (int n = 0; n < 4; ++n) {
        *(float2*)&o0[n * 8 + 2 * qid] = make_float2(o[n][0] * i0, o[n][1] * i0);
        *(float2*)&o1[n * 8 + 2 * qid] = make_float2(o[n][2] * i1, o[n][3] * i1);
    }
}

// ---------------- residual add + LayerNorm (+ optional pos-added copy) ------
template <int WPOS>
__global__ void __launch_bounds__(256) add_ln_kernel(
    const float* __restrict__ X, const float* __restrict__ R,
    const float* __restrict__ g, const float* __restrict__ bb,
    float* __restrict__ out,
    const float* __restrict__ pos, float* __restrict__ out2) {
    const int r = blockIdx.x, t = threadIdx.x;
    const float v = X[(size_t)r * CC + t] + R[(size_t)r * CC + t];
    float s = v, s2 = v * v;
#pragma unroll
    for (int off = 16; off; off >>= 1) {
        s  += __shfl_xor_sync(0xffffffffu, s,  off);
        s2 += __shfl_xor_sync(0xffffffffu, s2, off);
    }
    __shared__ float sh[8], sh2[8];
    const int w = t >> 5, ln = t & 31;
    if (ln == 0) { sh[w] = s; sh2[w] = s2; }
    __syncthreads();
    if (t == 0) {
        float a = 0.f, b2 = 0.f;
#pragma unroll
        for (int i = 0; i < 8; ++i) { a += sh[i]; b2 += sh2[i]; }
        const float mean = a * (1.f / 256.f);
        const float var = b2 * (1.f / 256.f) - mean * mean;
        sh[0] = mean;
        sh2[0] = rsqrtf(var + 1e-5f);
    }
    __syncthreads();
    const float mean = sh[0], inv = sh2[0];
    const float y = (v - mean) * inv * g[t] + bb[t];
    out[(size_t)r * CC + t] = y;
    if (WPOS)
        out2[(size_t)r * CC + t] = y + pos[(size_t)r * CC + t];
}

// ---------------- MS deformable sampling (fused off|aw layout, stride 384) ---
__global__ void __launch_bounds__(256) deform_kernel(
    const float* __restrict__ value,   // [B*LSRC, 256]
    const float* __restrict__ offaw,   // [M1, 384]
    const float* __restrict__ refp,    // [B, LQ, L, 2]
    float* __restrict__ out) {         // [M1, 256]
    const int wid = blockIdx.x * 8 + (threadIdx.x >> 5);
    const int lane = threadIdx.x & 31;
    const int h = wid & 7;
    const int q = (wid >> 3) & 1023;
    const int b = wid >> 13;

    const float* rowp = offaw + (size_t)(b * LQn + q) * 384;
    const float* ar = rowp + 256 + h * 16;
    const float logit = (lane < 16) ? ar[lane] : -1e30f;
    float mx = logit;
#pragma unroll
    for (int o = 16; o; o >>= 1)
        mx = fmaxf(mx, __shfl_xor_sync(0xffffffffu, mx, o));
    float e = (lane < 16) ? __expf(logit - mx) : 0.f;
    float se = e;
#pragma unroll
    for (int o = 16; o; o >>= 1) se += __shfl_xor_sync(0xffffffffu, se, o);
    const float p = e / se;

    const int   SZ[4] = {128, 64, 32, 16};
    const int   ST[4] = {0, 16384, 20480, 21504};
    const float* offr = rowp + h * 32;
    const float* refr = refp + (size_t)(b * LQn + q) * 8;

    float acc = 0.f;
#pragma unroll
    for (int l = 0; l < 4; ++l) {
        const int Wl = SZ[l];
        const float Wf = (float)Wl;
        const float rx = refr[l * 2 + 0];
        const float ry = refr[l * 2 + 1];
        const float* vb =
            value + ((size_t)b * LSRC + ST[l]) * 256 + h * 32 + lane;
#pragma unroll
        for (int pt = 0; pt < 4; ++pt) {
            const float ox = offr[(l * 4 + pt) * 2 + 0];
            const float oy = offr[(l * 4 + pt) * 2 + 1];
            const float x = (rx + ox / Wf) * Wf - 0.5f;
            const float y = (ry + oy / Wf) * Wf - 0.5f;
            const float x0f = floorf(x), y0f = floorf(y);
            const int x0 = (int)x0f, y0 = (int)y0f;
            const float wx1 = x - x0f, wx0 = 1.f - wx1;
            const float wy1 = y - y0f, wy0 = 1.f - wy1;
            const float aw = __shfl_sync(0xffffffffu, p, l * 4 + pt);

            if ((unsigned)x0 < (unsigned)Wl && (unsigned)y0 < (unsigned)Wl)
                acc = fmaf(aw * (wx0 * wy0),
                           vb[((size_t)y0 * Wl + x0) * 256], acc);
            if ((unsigned)(x0 + 1) < (unsigned)Wl && (unsigned)y0 < (unsigned)Wl)
                acc = fmaf(aw * (wx1 * wy0),
                           vb[((size_t)y0 * Wl + x0 + 1) * 256], acc);
            if ((unsigned)x0 < (unsigned)Wl && (unsigned)(y0 + 1) < (unsigned)Wl)
                acc = fmaf(aw * (wx0 * wy1),
                           vb[((size_t)(y0 + 1) * Wl + x0) * 256], acc);
            if ((unsigned)(x0 + 1) < (unsigned)Wl &&
                (unsigned)(y0 + 1) < (unsigned)Wl)
                acc = fmaf(aw * (wx1 * wy1),
                           vb[((size_t)(y0 + 1) * Wl + x0 + 1) * 256], acc);
        }
    }
    out[(size_t)(b * LQn + q) * 256 + h * 32 + lane] = acc;
}

// ---------------- launch (serial, single stream) -----------------------------
extern "C" void kernel_launch(void* const* d_in, const int* in_sizes, int n_in,
                              void* d_out, int out_size) {
    const float* tgt   = (const float*)d_in[0];
    const float* qpos  = (const float*)d_in[1];
    const float* refp  = (const float*)d_in[2];
    const float* src   = (const float*)d_in[3];
    const float* in_w  = (const float*)d_in[4];
    const float* in_b  = (const float*)d_in[5];
    const float* sa_w  = (const float*)d_in[6];
    const float* sa_b  = (const float*)d_in[7];
    const float* off_w = (const float*)d_in[8];
    const float* off_b = (const float*)d_in[9];
    const float* aw_w  = (const float*)d_in[10];
    const float* aw_b  = (const float*)d_in[11];
    const float* val_w = (const float*)d_in[12];
    const float* val_b = (const float*)d_in[13];
    const float* co_w  = (const float*)d_in[14];
    const float* co_b  = (const float*)d_in[15];
    const float* ln1_g = (const float*)d_in[16];
    const float* ln1_b = (const float*)d_in[17];
    const float* ln2_g = (const float*)d_in[18];
    const float* ln2_b = (const float*)d_in[19];
    const float* ln3_g = (const float*)d_in[20];
    const float* ln3_b = (const float*)d_in[21];
    const float* f1_w  = (const float*)d_in[22];
    const float* f1_b  = (const float*)d_in[23];
    const float* f2_w  = (const float*)d_in[24];
    const float* f2_b  = (const float*)d_in[25];
    float* out = (float*)d_out;

    float* s = nullptr;
    cudaGetSymbolAddress((void**)&s, g_scratch);
    float* qk    = s + OF_QK;
    float* qkp   = s + OF_QKP;
    float* vbuf  = s + OF_V;
    float* attn  = s + OF_ATT;
    float* tgta  = s + OF_TGA;
    float* q2    = s + OF_Q2;
    float* value = s + OF_VAL;
    float* dfo   = s + OF_DFO;
    float* offaw = s + OF_OFW;
    float* tmp   = s + OF_TMP;
    float* tgtb  = s + OF_TGB;
    float* ffh   = s + OF_FFH;
    float* wcat  = s + OF_WCT;
    float* bcat  = s + OF_BCT;

    const int n4 = M1 * CC / 4;

    cudaMemcpyAsync(wcat, off_w, (size_t)256 * CC * sizeof(float),
                    cudaMemcpyDeviceToDevice, 0);
    cudaMemcpyAsync(wcat + 256 * CC, aw_w, (size_t)128 * CC * sizeof(float),
                    cudaMemcpyDeviceToDevice, 0);
    cudaMemcpyAsync(bcat, off_b, 256 * sizeof(float),
                    cudaMemcpyDeviceToDevice, 0);
    cudaMemcpyAsync(bcat + 256, aw_b, 128 * sizeof(float),
                    cudaMemcpyDeviceToDevice, 0);

    // --- self-attention block ---
    add_vec_kernel<<<(n4 + 255) / 256, 256>>>(
        (const float4*)tgt, (const float4*)qpos, (float4*)qk, n4);
    tf32_gemm64_kernel<0><<<dim3(512 / 64, M1 / 64), 256>>>(
        qk, in_w, in_b, qkp, CC, 512);
    tf32_gemm64_kernel<0><<<dim3(CC / 64, M1 / 64), 256>>>(
        tgt, in_w + 512 * CC, in_b + 512, vbuf, CC, CC);
    mha_attn_kernel<<<dim3(LQn / 64, HH, BQ), 128>>>(qkp, vbuf, attn);
    tf32_gemm64_kernel<0><<<dim3(CC / 64, M1 / 64), 256>>>(
        attn, sa_w, sa_b, tmp, CC, CC);
    add_ln_kernel<1><<<M1, 256>>>(tmp, tgt, ln2_g, ln2_b, tgta, qpos, q2);

    // value projection
    tf32_gemm_kernel<0><<<dim3(CC / 128, MS / 128), 256>>>(
        src, val_w, val_b, value, CC, CC);

    // --- deformable cross-attention block ---
    tf32_gemm64_kernel<0><<<dim3(384 / 64, M1 / 64), 256>>>(
        q2, wcat, bcat, offaw, CC, 384);
    deform_kernel<<<(BQ * LQn * HH) / 8, 256>>>(value, offaw, refp, dfo);
    tf32_gemm64_kernel<0><<<dim3(CC / 64, M1 / 64), 256>>>(
        dfo, co_w, co_b, tmp, CC, CC);
    add_ln_kernel<0><<<M1, 256>>>(tmp, tgta, ln1_g, ln1_b, tgtb,
                                  nullptr, nullptr);

    // --- FFN block ---
    tf32_gemm_kernel<1><<<dim3(DFFn / 128, M1 / 128), 256>>>(
        tgtb, f1_w, f1_b, ffh, CC, DFFn);
    tf32_gemm64_kernel<0><<<dim3(CC / 64, M1 / 64), 256>>>(
        ffh, f2_w, f2_b, tmp, DFFn, CC);
    add_ln_kernel<0><<<M1, 256>>>(tmp, tgtb, ln3_g, ln3_b, out,
                                  nullptr, nullptr);
}

// round 17
// speedup vs baseline: 1.4726x; 1.0571x over previous
#include <cuda_runtime.h>
#include <math.h>
#include <stdint.h>

// ---------------- problem constants ----------------
#define BQ   4
#define LQn  1024
#define CC   256
#define HH   8
#define DFFn 1024
#define LSRC 21760
#define M1   (BQ * LQn)     // 4096 query rows
#define MS   (BQ * LSRC)    // 87040 source rows

typedef unsigned long long u64;

// ---------------- scratch (static device global, no allocs) ----------------
static constexpr size_t OF_QK  = 0;
static constexpr size_t OF_QKP = OF_QK  + (size_t)M1 * CC;      // Q|K packed, 512 cols
static constexpr size_t OF_V   = OF_QKP + (size_t)M1 * 512;
static constexpr size_t OF_ATT = OF_V   + (size_t)M1 * CC;
static constexpr size_t OF_TGA = OF_ATT + (size_t)M1 * CC;
static constexpr size_t OF_Q2  = OF_TGA + (size_t)M1 * CC;
static constexpr size_t OF_VAL = OF_Q2  + (size_t)M1 * CC;
static constexpr size_t OF_DFO = OF_VAL + (size_t)MS * CC;
static constexpr size_t OF_OFW = OF_DFO + (size_t)M1 * CC;      // off|aw out, stride 384
static constexpr size_t OF_TMP = OF_OFW + (size_t)M1 * 384;
static constexpr size_t OF_TGB = OF_TMP + (size_t)M1 * CC;
static constexpr size_t OF_FFH = OF_TGB + (size_t)M1 * CC;
static constexpr size_t OF_WCT = OF_FFH + (size_t)M1 * DFFn;    // concat off_w|aw_w [384,256]
static constexpr size_t OF_BCT = OF_WCT + (size_t)384 * CC;     // concat bias [384]
static constexpr size_t SCRATCH_TOTAL = OF_BCT + 384;

__device__ __align__(16) float g_scratch[SCRATCH_TOTAL];

// ---------------- small helpers ----------------
__device__ __forceinline__ void cp_async16(void* s, const void* g) {
    unsigned sa = (unsigned)__cvta_generic_to_shared(s);
    asm volatile("cp.async.ca.shared.global [%0], [%1], 16;" :: "r"(sa), "l"(g));
}
__device__ __forceinline__ void ldsm_x4(unsigned* r, unsigned addr) {
    asm volatile(
        "ldmatrix.sync.aligned.m8n8.x4.shared.b16 {%0,%1,%2,%3}, [%4];"
        : "=r"(r[0]), "=r"(r[1]), "=r"(r[2]), "=r"(r[3]) : "r"(addr));
}
#define MMA_TF32(accp, a0, a1, a2, a3, b0, b1)                               \
    asm volatile(                                                            \
        "mma.sync.aligned.m16n8k8.row.col.f32.tf32.tf32.f32 "                \
        "{%0,%1,%2,%3}, {%4,%5,%6,%7}, {%8,%9}, {%0,%1,%2,%3};"              \
        : "+f"((accp)[0]), "+f"((accp)[1]), "+f"((accp)[2]), "+f"((accp)[3]) \
        : "r"(a0), "r"(a1), "r"(a2), "r"(a3), "r"(b0), "r"(b1))

// ---------------- elementwise add (float4) ----------------
__global__ void add_vec_kernel(const float4* __restrict__ a,
                               const float4* __restrict__ b,
                               float4* __restrict__ o, int n4) {
    int i = blockIdx.x * blockDim.x + threadIdx.x;
    if (i < n4) {
        float4 x = a[i], y = b[i];
        o[i] = make_float4(x.x + y.x, x.y + y.y, x.z + y.z, x.w + y.w);
    }
}

// ---------------- tf32 GEMM, 128x128 tiles, 3-stage, ldmatrix ---------------
template <int ACT>
__global__ void __launch_bounds__(256, 2) tf32_gemm_kernel(
    const float* __restrict__ A, const float* __restrict__ W,
    const float* __restrict__ bias, float* __restrict__ C,
    int K, int N) {
    __shared__ __align__(16) float sA[3][128 * 20];
    __shared__ __align__(16) float sB[3][128 * 20];

    const int tid = threadIdx.x;
    const int m0 = blockIdx.y << 7;
    const int n0 = blockIdx.x << 7;
    const int warp = tid >> 5, lane = tid & 31;
    const int wm = warp >> 2, wn = warp & 3;
    const int grp = lane >> 2, qid = lane & 3;

    const unsigned sA32 = (unsigned)__cvta_generic_to_shared(&sA[0][0]);
    const unsigned sB32 = (unsigned)__cvta_generic_to_shared(&sB[0][0]);
    const unsigned STG = 128 * 20 * 4;

    unsigned aoff[4], boff[4];
#pragma unroll
    for (int mi = 0; mi < 4; ++mi)
        aoff[mi] = (unsigned)((wm * 64 + mi * 16 + ((lane >> 3) & 1) * 8 +
                               (lane & 7)) * 80 + ((lane >> 4) << 4));
#pragma unroll
    for (int ni = 0; ni < 4; ++ni)
        boff[ni] = (unsigned)((wn * 32 + ni * 8 + (lane & 7)) * 80 +
                              ((lane >> 3) << 4));

    float acc[4][4][4];
#pragma unroll
    for (int mi = 0; mi < 4; ++mi)
#pragma unroll
        for (int ni = 0; ni < 4; ++ni)
#pragma unroll
            for (int r = 0; r < 4; ++r) acc[mi][ni][r] = 0.f;

    const int srow = tid >> 2;
    const int scol = (tid & 3) << 2;
    const float* Abase = A + (size_t)m0 * K;
    const float* Bbase = W + (size_t)n0 * K;

#define LOAD128(t, buf)                                                     \
    do {                                                                    \
        const float* Ab = Abase + (size_t)(t) * 16;                         \
        const float* Bb = Bbase + (size_t)(t) * 16;                         \
        _Pragma("unroll")                                                   \
        for (int i = 0; i < 2; ++i) {                                       \
            int row = i * 64 + srow;                                        \
            cp_async16(&sA[buf][row * 20 + scol], Ab + (size_t)row * K + scol); \
            cp_async16(&sB[buf][row * 20 + scol], Bb + (size_t)row * K + scol); \
        }                                                                   \
    } while (0)

    const int T = K >> 4;
    LOAD128(0, 0);
    asm volatile("cp.async.commit_group;" ::: "memory");
    LOAD128(1, 1);
    asm volatile("cp.async.commit_group;" ::: "memory");

    for (int t = 0; t < T; ++t) {
        asm volatile("cp.async.wait_group 1;" ::: "memory");
        __syncthreads();

        const unsigned aBase = sA32 + (unsigned)(t % 3) * STG;
        const unsigned bBase = sB32 + (unsigned)(t % 3) * STG;
        unsigned a[4][2][4], b[4][4];
#pragma unroll
        for (int mi = 0; mi < 4; ++mi) {
            ldsm_x4(a[mi][0], aBase + aoff[mi]);
            ldsm_x4(a[mi][1], aBase + aoff[mi] + 32);
        }
#pragma unroll
        for (int ni = 0; ni < 4; ++ni)
            ldsm_x4(b[ni], bBase + boff[ni]);

#pragma unroll
        for (int s = 0; s < 2; ++s)
#pragma unroll
            for (int mi = 0; mi < 4; ++mi)
#pragma unroll
                for (int ni = 0; ni < 4; ++ni)
                    MMA_TF32(acc[mi][ni],
                             a[mi][s][0], a[mi][s][1], a[mi][s][2], a[mi][s][3],
                             b[ni][2 * s], b[ni][2 * s + 1]);

        const int tn = t + 2;
        if (tn < T) LOAD128(tn, tn % 3);
        asm volatile("cp.async.commit_group;" ::: "memory");
    }
#undef LOAD128

#pragma unroll
    for (int mi = 0; mi < 4; ++mi) {
        const int row = m0 + wm * 64 + mi * 16 + grp;
#pragma unroll
        for (int ni = 0; ni < 4; ++ni) {
            const int col = n0 + wn * 32 + ni * 8 + (qid << 1);
            const float2 bb = *(const float2*)(bias + col);
            float2 v0, v1;
            v0.x = acc[mi][ni][0] + bb.x; v0.y = acc[mi][ni][1] + bb.y;
            v1.x = acc[mi][ni][2] + bb.x; v1.y = acc[mi][ni][3] + bb.y;
            if (ACT) {
                v0.x = fmaxf(v0.x, 0.f); v0.y = fmaxf(v0.y, 0.f);
                v1.x = fmaxf(v1.x, 0.f); v1.y = fmaxf(v1.y, 0.f);
            }
            *(float2*)(C + (size_t)row * N + col) = v0;
            *(float2*)(C + (size_t)(row + 8) * N + col) = v1;
        }
    }
}

// ---------------- tf32 GEMM, 64x64 tiles, 256 thr, 4-stage, ldmatrix --------
template <int ACT>
__global__ void __launch_bounds__(256) tf32_gemm64_kernel(
    const float* __restrict__ A, const float* __restrict__ W,
    const float* __restrict__ bias, float* __restrict__ C,
    int K, int N) {
    __shared__ __align__(16) float sA[4][64 * 20];
    __shared__ __align__(16) float sB[4][64 * 20];

    const int tid = threadIdx.x;
    const int m0 = blockIdx.y << 6;
    const int n0 = blockIdx.x << 6;
    const int warp = tid >> 5, lane = tid & 31;
    const int wm = warp >> 2, wn = warp & 3;
    const int grp = lane >> 2, qid = lane & 3;
    const int srow = tid >> 2;
    const int scol = (tid & 3) << 2;

    const unsigned sA32 = (unsigned)__cvta_generic_to_shared(&sA[0][0]);
    const unsigned sB32 = (unsigned)__cvta_generic_to_shared(&sB[0][0]);
    const unsigned STG = 64 * 20 * 4;

    unsigned aoff[2], boff[2];
#pragma unroll
    for (int mi = 0; mi < 2; ++mi)
        aoff[mi] = (unsigned)((wm * 32 + mi * 16 + ((lane >> 3) & 1) * 8 +
                               (lane & 7)) * 80 + ((lane >> 4) << 4));
#pragma unroll
    for (int ni = 0; ni < 2; ++ni)
        boff[ni] = (unsigned)((wn * 16 + ni * 8 + (lane & 7)) * 80 +
                              ((lane >> 3) << 4));

    const float* Abase = A + (size_t)m0 * K;
    const float* Bbase = W + (size_t)n0 * K;

    float acc[2][2][4];
#pragma unroll
    for (int mi = 0; mi < 2; ++mi)
#pragma unroll
        for (int ni = 0; ni < 2; ++ni)
#pragma unroll
            for (int r = 0; r < 4; ++r) acc[mi][ni][r] = 0.f;

#define LOAD64(t, buf)                                                       \
    do {                                                                     \
        const float* Ab = Abase + (size_t)(t) * 16;                          \
        const float* Bb = Bbase + (size_t)(t) * 16;                          \
        cp_async16(&sA[buf][srow * 20 + scol], Ab + (size_t)srow * K + scol);\
        cp_async16(&sB[buf][srow * 20 + scol], Bb + (size_t)srow * K + scol);\
    } while (0)

    const int T = K >> 4;
    LOAD64(0, 0);
    asm volatile("cp.async.commit_group;" ::: "memory");
    LOAD64(1, 1);
    asm volatile("cp.async.commit_group;" ::: "memory");
    LOAD64(2, 2);
    asm volatile("cp.async.commit_group;" ::: "memory");

    for (int t = 0; t < T; ++t) {
        asm volatile("cp.async.wait_group 2;" ::: "memory");
        __syncthreads();

        const unsigned aBase = sA32 + (unsigned)(t & 3) * STG;
        const unsigned bBase = sB32 + (unsigned)(t & 3) * STG;
        unsigned a[2][2][4], b[2][4];
#pragma unroll
        for (int mi = 0; mi < 2; ++mi) {
            ldsm_x4(a[mi][0], aBase + aoff[mi]);
            ldsm_x4(a[mi][1], aBase + aoff[mi] + 32);
        }
#pragma unroll
        for (int ni = 0; ni < 2; ++ni)
            ldsm_x4(b[ni], bBase + boff[ni]);

#pragma unroll
        for (int s = 0; s < 2; ++s)
#pragma unroll
            for (int mi = 0; mi < 2; ++mi)
#pragma unroll
                for (int ni = 0; ni < 2; ++ni)
                    MMA_TF32(acc[mi][ni],
                             a[mi][s][0], a[mi][s][1], a[mi][s][2], a[mi][s][3],
                             b[ni][2 * s], b[ni][2 * s + 1]);

        const int tn = t + 3;
        if (tn < T) LOAD64(tn, tn & 3);
        asm volatile("cp.async.commit_group;" ::: "memory");
    }
#undef LOAD64

#pragma unroll
    for (int mi = 0; mi < 2; ++mi) {
        const int row = m0 + wm * 32 + mi * 16 + grp;
#pragma unroll
        for (int ni = 0; ni < 2; ++ni) {
            const int col = n0 + wn * 16 + ni * 8 + (qid << 1);
            const float2 bb = *(const float2*)(bias + col);
            float2 v0, v1;
            v0.x = acc[mi][ni][0] + bb.x; v0.y = acc[mi][ni][1] + bb.y;
            v1.x = acc[mi][ni][2] + bb.x; v1.y = acc[mi][ni][3] + bb.y;
            if (ACT) {
                v0.x = fmaxf(v0.x, 0.f); v0.y = fmaxf(v0.y, 0.f);
                v1.x = fmaxf(v1.x, 0.f); v1.y = fmaxf(v1.y, 0.f);
            }
            *(float2*)(C + (size_t)row * N + col) = v0;
            *(float2*)(C + (size_t)(row + 8) * N + col) = v1;
        }
    }
}

// ---------------- flash attention via mma.sync (tf32), v2 -------------------
// Block: 128 queries of one (b,h), 4 warps x 32 queries (2 m-tiles each).
// K/V B-fragments shared across both m-tiles; K/V tiles double-buffered.
// Dynamic smem layout (floats):
//   [0, 9216): K0(64x36) | V0(64x36) | K1(64x36) | V1(64x36)   (2304 each)
//   [9216, 17920): staging Q[128][36] (4608), later P[128][68] (8704)
__global__ void __launch_bounds__(128) mha_attn_kernel(
    const float* __restrict__ QK, const float* __restrict__ V,
    float* __restrict__ Og) {
    extern __shared__ __align__(16) float smem[];
    const int b = blockIdx.z, h = blockIdx.y;
    const int q0 = blockIdx.x << 7;
    const int tid = threadIdx.x;
    const int warp = tid >> 5, lane = tid & 31;
    const int grp = lane >> 2, qid = lane & 3;

    const unsigned smem32 = (unsigned)__cvta_generic_to_shared(smem);
    const unsigned spq32 = smem32 + 9216 * 4;
    float* const sPQ = smem + 9216;

    // ---- load Q tile (128x32, pitch 36) ----
    {
        const float* g = QK + (size_t)(b * LQn + q0 + tid) * 512 + h * 32;
        float* dq = sPQ + tid * 36;
#pragma unroll
        for (int c = 0; c < 32; c += 4) cp_async16(dq + c, g + c);
    }
    asm volatile("cp.async.commit_group;" ::: "memory");

    // ---- load K/V tile 0 into buf 0 ----
#define LOADKV(kt, buf)                                                      \
    do {                                                                     \
        const int r = tid >> 1;                                              \
        const int c = (tid & 1) << 4;                                        \
        const size_t row = (size_t)(b * LQn + (kt) * 64 + r);                \
        const float* gk = QK + row * 512 + 256 + h * 32 + c;                 \
        const float* gv = V + row * 256 + h * 32 + c;                        \
        float* dk = smem + (buf) * 4608 + r * 36 + c;                        \
        float* dv = smem + (buf) * 4608 + 2304 + r * 36 + c;                 \
        cp_async16(dk, gk); cp_async16(dk + 4, gk + 4);                      \
        cp_async16(dk + 8, gk + 8); cp_async16(dk + 12, gk + 12);            \
        cp_async16(dv, gv); cp_async16(dv + 4, gv + 4);                      \
        cp_async16(dv + 8, gv + 8); cp_async16(dv + 12, gv + 12);            \
    } while (0)

    LOADKV(0, 0);
    asm volatile("cp.async.commit_group;" ::: "memory");
    asm volatile("cp.async.wait_group 0;" ::: "memory");
    __syncthreads();

    // ---- Q fragments: 2 m-tiles x 4 ksteps, pre-scaled ----
    const float scale = 0.17677669529663687f;
    unsigned qf[2][4][4];
#pragma unroll
    for (int mi = 0; mi < 2; ++mi) {
        const unsigned base = spq32 +
            (unsigned)((warp * 32 + mi * 16 + ((lane >> 3) & 1) * 8 +
                        (lane & 7)) * 144 + ((lane >> 4) << 4));
#pragma unroll
        for (int ks = 0; ks < 4; ++ks) {
            ldsm_x4(qf[mi][ks], base + ks * 32);
#pragma unroll
            for (int j = 0; j < 4; ++j)
                qf[mi][ks][j] =
                    __float_as_uint(__uint_as_float(qf[mi][ks][j]) * scale);
        }
    }
    __syncthreads();   // all warps done reading Q before region reused as P

    float o[2][4][4];
#pragma unroll
    for (int mi = 0; mi < 2; ++mi)
#pragma unroll
        for (int n = 0; n < 4; ++n)
#pragma unroll
            for (int j = 0; j < 4; ++j) o[mi][n][j] = 0.f;
    float mM[2][2] = {{-1e30f, -1e30f}, {-1e30f, -1e30f}};
    float lL[2][2] = {{0.f, 0.f}, {0.f, 0.f}};

    const unsigned kfoff = (unsigned)((lane & 7) * 144 + ((lane >> 3) << 4));
    unsigned pfoff[2];
#pragma unroll
    for (int mi = 0; mi < 2; ++mi)
        pfoff[mi] = spq32 +
            (unsigned)((warp * 32 + mi * 16 + ((lane >> 3) & 1) * 8 +
                        (lane & 7)) * 272 + ((lane >> 4) << 4));

#pragma unroll 1
    for (int kt = 0; kt < 16; ++kt) {
        if (kt + 1 < 16) {
            LOADKV(kt + 1, (kt + 1) & 1);
            asm volatile("cp.async.commit_group;" ::: "memory");
            asm volatile("cp.async.wait_group 1;" ::: "memory");
        } else {
            asm volatile("cp.async.wait_group 0;" ::: "memory");
        }
        __syncthreads();

        const unsigned kBase = smem32 + (unsigned)((kt & 1) * 4608 * 4);
        const float* sV = smem + (kt & 1) * 4608 + 2304;

        // ---- S = Q @ K^T, both m-tiles share K B-frags ----
        float sc[2][8][4];
#pragma unroll
        for (int mi = 0; mi < 2; ++mi)
#pragma unroll
            for (int nt = 0; nt < 8; ++nt)
#pragma unroll
                for (int j = 0; j < 4; ++j) sc[mi][nt][j] = 0.f;
#pragma unroll
        for (int s = 0; s < 2; ++s)
#pragma unroll
            for (int nt = 0; nt < 8; ++nt) {
                unsigned bf[4];
                ldsm_x4(bf, kBase + kfoff + (unsigned)(nt * 8 * 144 + s * 64));
#pragma unroll
                for (int mi = 0; mi < 2; ++mi) {
                    MMA_TF32(sc[mi][nt], qf[mi][2 * s][0], qf[mi][2 * s][1],
                             qf[mi][2 * s][2], qf[mi][2 * s][3],
                             bf[0], bf[1]);
                    MMA_TF32(sc[mi][nt], qf[mi][2 * s + 1][0],
                             qf[mi][2 * s + 1][1], qf[mi][2 * s + 1][2],
                             qf[mi][2 * s + 1][3], bf[2], bf[3]);
                }
            }

        // ---- online softmax per m-tile, write P strip ----
#pragma unroll
        for (int mi = 0; mi < 2; ++mi) {
            float r0 = -1e30f, r1 = -1e30f;
#pragma unroll
            for (int nt = 0; nt < 8; ++nt) {
                r0 = fmaxf(r0, fmaxf(sc[mi][nt][0], sc[mi][nt][1]));
                r1 = fmaxf(r1, fmaxf(sc[mi][nt][2], sc[mi][nt][3]));
            }
            r0 = fmaxf(r0, __shfl_xor_sync(0xffffffffu, r0, 1));
            r0 = fmaxf(r0, __shfl_xor_sync(0xffffffffu, r0, 2));
            r1 = fmaxf(r1, __shfl_xor_sync(0xffffffffu, r1, 1));
            r1 = fmaxf(r1, __shfl_xor_sync(0xffffffffu, r1, 2));
            const float mn0 = fmaxf(mM[mi][0], r0);
            const float mn1 = fmaxf(mM[mi][1], r1);
            const float c0 = __expf(mM[mi][0] - mn0);
            const float c1 = __expf(mM[mi][1] - mn1);
            mM[mi][0] = mn0; mM[mi][1] = mn1;
            float ps0 = 0.f, ps1 = 0.f;
#pragma unroll
            for (int nt = 0; nt < 8; ++nt) {
                sc[mi][nt][0] = __expf(sc[mi][nt][0] - mn0); ps0 += sc[mi][nt][0];
                sc[mi][nt][1] = __expf(sc[mi][nt][1] - mn0); ps0 += sc[mi][nt][1];
                sc[mi][nt][2] = __expf(sc[mi][nt][2] - mn1); ps1 += sc[mi][nt][2];
                sc[mi][nt][3] = __expf(sc[mi][nt][3] - mn1); ps1 += sc[mi][nt][3];
            }
            ps0 += __shfl_xor_sync(0xffffffffu, ps0, 1);
            ps0 += __shfl_xor_sync(0xffffffffu, ps0, 2);
            ps1 += __shfl_xor_sync(0xffffffffu, ps1, 1);
            ps1 += __shfl_xor_sync(0xffffffffu, ps1, 2);
            lL[mi][0] = lL[mi][0] * c0 + ps0;
            lL[mi][1] = lL[mi][1] * c1 + ps1;
#pragma unroll
            for (int n = 0; n < 4; ++n) {
                o[mi][n][0] *= c0; o[mi][n][1] *= c0;
                o[mi][n][2] *= c1; o[mi][n][3] *= c1;
            }
            const int pr = warp * 32 + mi * 16 + grp;
#pragma unroll
            for (int nt = 0; nt < 8; ++nt) {
                *(float2*)&sPQ[pr * 68 + nt * 8 + 2 * qid] =
                    make_float2(sc[mi][nt][0], sc[mi][nt][1]);
                *(float2*)&sPQ[(pr + 8) * 68 + nt * 8 + 2 * qid] =
                    make_float2(sc[mi][nt][2], sc[mi][nt][3]);
            }
        }
        __syncwarp();

        // ---- O += P @ V, both m-tiles share V B-frags ----
#pragma unroll
        for (int kk = 0; kk < 8; ++kk) {
            unsigned vb[4][2];
#pragma unroll
            for (int n = 0; n < 4; ++n) {
                vb[n][0] = __float_as_uint(
                    sV[(kk * 8 + qid) * 36 + n * 8 + grp]);
                vb[n][1] = __float_as_uint(
                    sV[(kk * 8 + qid + 4) * 36 + n * 8 + grp]);
            }
#pragma unroll
            for (int mi = 0; mi < 2; ++mi) {
                unsigned af[4];
                ldsm_x4(af, pfoff[mi] + (unsigned)(kk * 32));
#pragma unroll
                for (int n = 0; n < 4; ++n)
                    MMA_TF32(o[mi][n], af[0], af[1], af[2], af[3],
                             vb[n][0], vb[n][1]);
            }
        }
        __syncthreads();
    }
#undef LOADKV

    // ---- epilogue ----
#pragma unroll
    for (int mi = 0; mi < 2; ++mi) {
        const float i0 = 1.f / lL[mi][0], i1 = 1.f / lL[mi][1];
        const int row = b * LQn + q0 + warp * 32 + mi * 16 + grp;
        float* o0 = Og + (size_t)row * 256 + h * 32;
        float* o1 = Og + (size_t)(row + 8) * 256 + h * 32;
#pragma unroll
        for (int n = 0; n < 4; ++n) {
            *(float2*)&o0[n * 8 + 2 * qid] =
                make_float2(o[mi][n][0] * i0, o[mi][n][1] * i0);
            *(float2*)&o1[n * 8 + 2 * qid] =
                make_float2(o[mi][n][2] * i1, o[mi][n][3] * i1);
        }
    }
}

// ---------------- residual add + LayerNorm (+ optional pos-added copy) ------
template <int WPOS>
__global__ void __launch_bounds__(256) add_ln_kernel(
    const float* __restrict__ X, const float* __restrict__ R,
    const float* __restrict__ g, const float* __restrict__ bb,
    float* __restrict__ out,
    const float* __restrict__ pos, float* __restrict__ out2) {
    const int r = blockIdx.x, t = threadIdx.x;
    const float v = X[(size_t)r * CC + t] + R[(size_t)r * CC + t];
    float s = v, s2 = v * v;
#pragma unroll
    for (int off = 16; off; off >>= 1) {
        s  += __shfl_xor_sync(0xffffffffu, s,  off);
        s2 += __shfl_xor_sync(0xffffffffu, s2, off);
    }
    __shared__ float sh[8], sh2[8];
    const int w = t >> 5, ln = t & 31;
    if (ln == 0) { sh[w] = s; sh2[w] = s2; }
    __syncthreads();
    if (t == 0) {
        float a = 0.f, b2 = 0.f;
#pragma unroll
        for (int i = 0; i < 8; ++i) { a += sh[i]; b2 += sh2[i]; }
        const float mean = a * (1.f / 256.f);
        const float var = b2 * (1.f / 256.f) - mean * mean;
        sh[0] = mean;
        sh2[0] = rsqrtf(var + 1e-5f);
    }
    __syncthreads();
    const float mean = sh[0], inv = sh2[0];
    const float y = (v - mean) * inv * g[t] + bb[t];
    out[(size_t)r * CC + t] = y;
    if (WPOS)
        out2[(size_t)r * CC + t] = y + pos[(size_t)r * CC + t];
}

// ---------------- MS deformable sampling (fused off|aw layout, stride 384) ---
__global__ void __launch_bounds__(256) deform_kernel(
    const float* __restrict__ value,   // [B*LSRC, 256]
    const float* __restrict__ offaw,   // [M1, 384]
    const float* __restrict__ refp,    // [B, LQ, L, 2]
    float* __restrict__ out) {         // [M1, 256]
    const int wid = blockIdx.x * 8 + (threadIdx.x >> 5);
    const int lane = threadIdx.x & 31;
    const int h = wid & 7;
    const int q = (wid >> 3) & 1023;
    const int b = wid >> 13;

    const float* rowp = offaw + (size_t)(b * LQn + q) * 384;
    const float* ar = rowp + 256 + h * 16;
    const float logit = (lane < 16) ? ar[lane] : -1e30f;
    float mx = logit;
#pragma unroll
    for (int o = 16; o; o >>= 1)
        mx = fmaxf(mx, __shfl_xor_sync(0xffffffffu, mx, o));
    float e = (lane < 16) ? __expf(logit - mx) : 0.f;
    float se = e;
#pragma unroll
    for (int o = 16; o; o >>= 1) se += __shfl_xor_sync(0xffffffffu, se, o);
    const float p = e / se;

    const int   SZ[4] = {128, 64, 32, 16};
    const int   ST[4] = {0, 16384, 20480, 21504};
    const float* offr = rowp + h * 32;
    const float* refr = refp + (size_t)(b * LQn + q) * 8;

    float acc = 0.f;
#pragma unroll
    for (int l = 0; l < 4; ++l) {
        const int Wl = SZ[l];
        const float Wf = (float)Wl;
        const float rx = refr[l * 2 + 0];
        const float ry = refr[l * 2 + 1];
        const float* vb =
            value + ((size_t)b * LSRC + ST[l]) * 256 + h * 32 + lane;
#pragma unroll
        for (int pt = 0; pt < 4; ++pt) {
            const float ox = offr[(l * 4 + pt) * 2 + 0];
            const float oy = offr[(l * 4 + pt) * 2 + 1];
            const float x = (rx + ox / Wf) * Wf - 0.5f;
            const float y = (ry + oy / Wf) * Wf - 0.5f;
            const float x0f = floorf(x), y0f = floorf(y);
            const int x0 = (int)x0f, y0 = (int)y0f;
            const float wx1 = x - x0f, wx0 = 1.f - wx1;
            const float wy1 = y - y0f, wy0 = 1.f - wy1;
            const float aw = __shfl_sync(0xffffffffu, p, l * 4 + pt);

            if ((unsigned)x0 < (unsigned)Wl && (unsigned)y0 < (unsigned)Wl)
                acc = fmaf(aw * (wx0 * wy0),
                           vb[((size_t)y0 * Wl + x0) * 256], acc);
            if ((unsigned)(x0 + 1) < (unsigned)Wl && (unsigned)y0 < (unsigned)Wl)
                acc = fmaf(aw * (wx1 * wy0),
                           vb[((size_t)y0 * Wl + x0 + 1) * 256], acc);
            if ((unsigned)x0 < (unsigned)Wl && (unsigned)(y0 + 1) < (unsigned)Wl)
                acc = fmaf(aw * (wx0 * wy1),
                           vb[((size_t)(y0 + 1) * Wl + x0) * 256], acc);
            if ((unsigned)(x0 + 1) < (unsigned)Wl &&
                (unsigned)(y0 + 1) < (unsigned)Wl)
                acc = fmaf(aw * (wx1 * wy1),
                           vb[((size_t)(y0 + 1) * Wl + x0 + 1) * 256], acc);
        }
    }
    out[(size_t)(b * LQn + q) * 256 + h * 32 + lane] = acc;
}

// ---------------- launch (serial, single stream) -----------------------------
extern "C" void kernel_launch(void* const* d_in, const int* in_sizes, int n_in,
                              void* d_out, int out_size) {
    const float* tgt   = (const float*)d_in[0];
    const float* qpos  = (const float*)d_in[1];
    const float* refp  = (const float*)d_in[2];
    const float* src   = (const float*)d_in[3];
    const float* in_w  = (const float*)d_in[4];
    const float* in_b  = (const float*)d_in[5];
    const float* sa_w  = (const float*)d_in[6];
    const float* sa_b  = (const float*)d_in[7];
    const float* off_w = (const float*)d_in[8];
    const float* off_b = (const float*)d_in[9];
    const float* aw_w  = (const float*)d_in[10];
    const float* aw_b  = (const float*)d_in[11];
    const float* val_w = (const float*)d_in[12];
    const float* val_b = (const float*)d_in[13];
    const float* co_w  = (const float*)d_in[14];
    const float* co_b  = (const float*)d_in[15];
    const float* ln1_g = (const float*)d_in[16];
    const float* ln1_b = (const float*)d_in[17];
    const float* ln2_g = (const float*)d_in[18];
    const float* ln2_b = (const float*)d_in[19];
    const float* ln3_g = (const float*)d_in[20];
    const float* ln3_b = (const float*)d_in[21];
    const float* f1_w  = (const float*)d_in[22];
    const float* f1_b  = (const float*)d_in[23];
    const float* f2_w  = (const float*)d_in[24];
    const float* f2_b  = (const float*)d_in[25];
    float* out = (float*)d_out;

    float* s = nullptr;
    cudaGetSymbolAddress((void**)&s, g_scratch);
    float* qk    = s + OF_QK;
    float* qkp   = s + OF_QKP;
    float* vbuf  = s + OF_V;
    float* attn  = s + OF_ATT;
    float* tgta  = s + OF_TGA;
    float* q2    = s + OF_Q2;
    float* value = s + OF_VAL;
    float* dfo   = s + OF_DFO;
    float* offaw = s + OF_OFW;
    float* tmp   = s + OF_TMP;
    float* tgtb  = s + OF_TGB;
    float* ffh   = s + OF_FFH;
    float* wcat  = s + OF_WCT;
    float* bcat  = s + OF_BCT;

    const int n4 = M1 * CC / 4;
    const int MHA_SMEM = (9216 + 8704) * 4;   // 71680 B

    cudaFuncSetAttribute(mha_attn_kernel,
                         cudaFuncAttributeMaxDynamicSharedMemorySize,
                         MHA_SMEM);

    cudaMemcpyAsync(wcat, off_w, (size_t)256 * CC * sizeof(float),
                    cudaMemcpyDeviceToDevice, 0);
    cudaMemcpyAsync(wcat + 256 * CC, aw_w, (size_t)128 * CC * sizeof(float),
                    cudaMemcpyDeviceToDevice, 0);
    cudaMemcpyAsync(bcat, off_b, 256 * sizeof(float),
                    cudaMemcpyDeviceToDevice, 0);
    cudaMemcpyAsync(bcat + 256, aw_b, 128 * sizeof(float),
                    cudaMemcpyDeviceToDevice, 0);

    // --- self-attention block ---
    add_vec_kernel<<<(n4 + 255) / 256, 256>>>(
        (const float4*)tgt, (const float4*)qpos, (float4*)qk, n4);
    tf32_gemm64_kernel<0><<<dim3(512 / 64, M1 / 64), 256>>>(
        qk, in_w, in_b, qkp, CC, 512);
    tf32_gemm64_kernel<0><<<dim3(CC / 64, M1 / 64), 256>>>(
        tgt, in_w + 512 * CC, in_b + 512, vbuf, CC, CC);
    mha_attn_kernel<<<dim3(LQn / 128, HH, BQ), 128, MHA_SMEM>>>(
        qkp, vbuf, attn);
    tf32_gemm64_kernel<0><<<dim3(CC / 64, M1 / 64), 256>>>(
        attn, sa_w, sa_b, tmp, CC, CC);
    add_ln_kernel<1><<<M1, 256>>>(tmp, tgt, ln2_g, ln2_b, tgta, qpos, q2);

    // value projection
    tf32_gemm_kernel<0><<<dim3(CC / 128, MS / 128), 256>>>(
        src, val_w, val_b, value, CC, CC);

    // --- deformable cross-attention block ---
    tf32_gemm64_kernel<0><<<dim3(384 / 64, M1 / 64), 256>>>(
        q2, wcat, bcat, offaw, CC, 384);
    deform_kernel<<<(BQ * LQn * HH) / 8, 256>>>(value, offaw, refp, dfo);
    tf32_gemm64_kernel<0><<<dim3(CC / 64, M1 / 64), 256>>>(
        dfo, co_w, co_b, tmp, CC, CC);
    add_ln_kernel<0><<<M1, 256>>>(tmp, tgta, ln1_g, ln1_b, tgtb,
                                  nullptr, nullptr);

    // --- FFN block ---
    tf32_gemm_kernel<1><<<dim3(DFFn / 128, M1 / 128), 256>>>(
        tgtb, f1_w, f1_b, ffh, CC, DFFn);
    tf32_gemm64_kernel<0><<<dim3(CC / 64, M1 / 64), 256>>>(
        ffh, f2_w, f2_b, tmp, DFFn, CC);
    add_ln_kernel<0><<<M1, 256>>>(tmp, tgtb, ln3_g, ln3_b, out,
                                  nullptr, nullptr);
}